// round 7
// baseline (speedup 1.0000x reference)
#include <cuda_runtime.h>
#include <cuda_bf16.h>
#include <cuda_fp16.h>
#include <cstdint>

#define BB 64
#define NN 4096
#define DD 128
#define NS 8
#define SCALE 0.08838834764831845f

// ---------------- device scratch ----------------
__device__ float  g_keys[BB*NN*DD];      // fp32 keys (logit-sensitive)
__device__ __half g_vals[BB*NN*DD];      // fp16 values
__device__ float g_q[BB*NS*DD];
__device__ float g_slots[BB*NS*DD];
__device__ float g_upd[BB*NS*DD];    // UNNORMALIZED update accumulators
__device__ float g_rs[BB*NS];        // rowsum accumulators
#define WPITCH 136
#define WIMG   (128*WPITCH)
__device__ __nv_bfloat16 g_w_hi[2*WIMG];
__device__ __nv_bfloat16 g_w_lo[2*WIMG];

__device__ __forceinline__ uint32_t smem_u32(const void* p){
    uint32_t a;
    asm("{ .reg .u64 t; cvta.to.shared.u64 t, %1; cvt.u32.u64 %0, t; }" : "=r"(a) : "l"(p));
    return a;
}

#define LDSM4(r0,r1,r2,r3,addr) \
    asm volatile("ldmatrix.sync.aligned.m8n8.x4.shared.b16 {%0,%1,%2,%3}, [%4];" \
        : "=r"(r0),"=r"(r1),"=r"(r2),"=r"(r3) : "r"(addr))
#define MMA16816(c,a0,a1,a2,a3,b0,b1) \
    asm volatile("mma.sync.aligned.m16n8k16.row.col.f32.bf16.bf16.f32 " \
        "{%0,%1,%2,%3}, {%4,%5,%6,%7}, {%8,%9}, {%0,%1,%2,%3};" \
        : "+f"((c)[0]),"+f"((c)[1]),"+f"((c)[2]),"+f"((c)[3]) \
        : "r"(a0),"r"(a1),"r"(a2),"r"(a3),"r"(b0),"r"(b1))

#define S_BIAS  0
#define S_A_HI  1024
#define S_A_LO  (1024 + 34816)
#define S_W     (1024 + 2*34816)         // KH, KL, VH, VL
#define S_TOTAL (S_W + 4*34816)
#define APITCHB 272

__global__ __launch_bounds__(256) void export_kernel(float* __restrict__ dst){
    int i = blockIdx.x*256 + threadIdx.x;
    dst[i] = g_slots[i];
}

// ---------------- prep: Wk/Wv -> pitched bf16 hi/lo images ----------------
__global__ __launch_bounds__(256) void prep_w_kernel(const float* __restrict__ Wk,
                                                     const float* __restrict__ Wv){
    int i = blockIdx.x*256 + threadIdx.x;
    int m = i >> 14;
    int idx = i & 16383;
    int row = idx >> 7, k = idx & 127;
    float v = (m ? Wv : Wk)[row*128 + k];
    __nv_bfloat16 h = __float2bfloat16_rn(v);
    __nv_bfloat16 l = __float2bfloat16_rn(v - __bfloat162float(h));
    g_w_hi[m*WIMG + row*WPITCH + k] = h;
    g_w_lo[m*WIMG + row*WPITCH + k] = l;
}

// ---------------- kernel 1: LN(x) + K/V projection via mma.sync bf16x3 ----------------
// grid 1024, 256 threads (8 warps), 256 rows of x per CTA
__global__ __launch_bounds__(256, 1) void ln_kv_mma_kernel(
    const float* __restrict__ x,
    const float* __restrict__ bk, const float* __restrict__ bv,
    const float* __restrict__ gin, const float* __restrict__ bin)
{
    extern __shared__ __align__(1024) char smem[];
    const uint32_t sb = smem_u32(smem);
    const int tid = threadIdx.x;
    const int wid = tid >> 5, lane = tid & 31;

    if (tid < 128){
        ((float*)(smem + S_BIAS))[tid]       = bk[tid];
        ((float*)(smem + S_BIAS))[tid + 128] = bv[tid];
    }
    {
        uint4* dst = (uint4*)(smem + S_W);
        const uint4* hi4 = (const uint4*)g_w_hi;
        const uint4* lo4 = (const uint4*)g_w_lo;
        for (int i = tid; i < 2176; i += 256){
            dst[i]        = hi4[i];
            dst[2176 + i] = lo4[i];
            dst[4352 + i] = hi4[2176 + i];
            dst[6528 + i] = lo4[2176 + i];
        }
    }

    const int aRow  = (lane & 7) + ((lane >> 3) & 1) * 8;
    const int aKoff = (lane >> 4) * 16;
    const uint32_t aHiBase = sb + S_A_HI + (16*wid + aRow)*APITCHB + aKoff;
    const uint32_t aLoBase = sb + S_A_LO + (16*wid + aRow)*APITCHB + aKoff;
    const int bRow4 = (lane & 7) + ((lane >> 4) & 1) * 8;
    const int bK4   = ((lane >> 3) & 1) * 16;
    const float* bias = (const float*)(smem + S_BIAS);
    const int r0 = 16*wid + (lane >> 2);
    const int cc = 2*(lane & 3);

    #pragma unroll 1
    for (int t = 0; t < 2; t++){
        __syncthreads();
        // ---- LayerNorm: 2 threads per row ----
        {
            const int row = tid >> 1, half = tid & 1;
            const float* xr = x + ((size_t)(blockIdx.x*256 + t*128 + row))*128 + half*64;
            float4 v[16];
            float s = 0.f, ss = 0.f;
            #pragma unroll
            for (int j = 0; j < 16; j++){
                v[j] = ((const float4*)xr)[j];
                s  += v[j].x + v[j].y + v[j].z + v[j].w;
                ss += v[j].x*v[j].x + v[j].y*v[j].y + v[j].z*v[j].z + v[j].w*v[j].w;
            }
            s  += __shfl_xor_sync(0xffffffffu, s, 1);
            ss += __shfl_xor_sync(0xffffffffu, ss, 1);
            const float m = s * (1.f/128.f);
            const float rstd = rsqrtf(ss*(1.f/128.f) - m*m + 1e-5f);
            #pragma unroll
            for (int j = 0; j < 16; j++){
                const int k0 = half*64 + j*4;
                float4 g4 = ((const float4*)gin)[k0>>2];
                float4 b4 = ((const float4*)bin)[k0>>2];
                float n0 = (v[j].x - m)*rstd*g4.x + b4.x;
                float n1 = (v[j].y - m)*rstd*g4.y + b4.y;
                float n2 = (v[j].z - m)*rstd*g4.z + b4.z;
                float n3 = (v[j].w - m)*rstd*g4.w + b4.w;
                __nv_bfloat16 h0 = __float2bfloat16_rn(n0), h1 = __float2bfloat16_rn(n1);
                __nv_bfloat16 h2 = __float2bfloat16_rn(n2), h3 = __float2bfloat16_rn(n3);
                __nv_bfloat162 hA; hA.x = h0; hA.y = h1;
                __nv_bfloat162 hB; hB.x = h2; hB.y = h3;
                __nv_bfloat162 lA, lB;
                lA.x = __float2bfloat16_rn(n0 - __bfloat162float(h0));
                lA.y = __float2bfloat16_rn(n1 - __bfloat162float(h1));
                lB.x = __float2bfloat16_rn(n2 - __bfloat162float(h2));
                lB.y = __float2bfloat16_rn(n3 - __bfloat162float(h3));
                char* ahp = smem + S_A_HI + row*APITCHB + k0*2;
                char* alp = smem + S_A_LO + row*APITCHB + k0*2;
                *(__nv_bfloat162*)(ahp)     = hA;
                *(__nv_bfloat162*)(ahp + 4) = hB;
                *(__nv_bfloat162*)(alp)     = lA;
                *(__nv_bfloat162*)(alp + 4) = lB;
            }
        }
        __syncthreads();

        const size_t gb = (size_t)blockIdx.x * 32768 + (size_t)t * 16384;

        #pragma unroll 1
        for (int colb_i = 0; colb_i < 2; colb_i++){
            const int colb = colb_i * 64;
            const uint32_t wKh = sb + S_W + (colb + bRow4)*APITCHB + bK4;
            const uint32_t wKl = wKh + 34816;
            const uint32_t wVh = wKh + 69632;
            const uint32_t wVl = wKh + 104448;

            float accK[8][4], accV[8][4];
            #pragma unroll
            for (int nt = 0; nt < 8; nt++)
                #pragma unroll
                for (int e = 0; e < 4; e++){ accK[nt][e]=0.f; accV[nt][e]=0.f; }

            #pragma unroll
            for (int kc = 0; kc < 8; kc++){
                const uint32_t ko = kc*32;
                uint32_t ah0,ah1,ah2,ah3, al0,al1,al2,al3;
                LDSM4(ah0,ah1,ah2,ah3, aHiBase + ko);
                LDSM4(al0,al1,al2,al3, aLoBase + ko);
                #pragma unroll
                for (int ntp = 0; ntp < 4; ntp++){
                    const uint32_t no = ntp*(16*APITCHB) + ko;
                    uint32_t bh0,bh1,bh2,bh3, bl0,bl1,bl2,bl3;
                    LDSM4(bh0,bh1,bh2,bh3, wKh + no);
                    LDSM4(bl0,bl1,bl2,bl3, wKl + no);
                    MMA16816(accK[2*ntp],   ah0,ah1,ah2,ah3, bh0,bh1);
                    MMA16816(accK[2*ntp],   ah0,ah1,ah2,ah3, bl0,bl1);
                    MMA16816(accK[2*ntp],   al0,al1,al2,al3, bh0,bh1);
                    MMA16816(accK[2*ntp+1], ah0,ah1,ah2,ah3, bh2,bh3);
                    MMA16816(accK[2*ntp+1], ah0,ah1,ah2,ah3, bl2,bl3);
                    MMA16816(accK[2*ntp+1], al0,al1,al2,al3, bh2,bh3);
                    LDSM4(bh0,bh1,bh2,bh3, wVh + no);
                    LDSM4(bl0,bl1,bl2,bl3, wVl + no);
                    MMA16816(accV[2*ntp],   ah0,ah1,ah2,ah3, bh0,bh1);
                    MMA16816(accV[2*ntp],   ah0,ah1,ah2,ah3, bl0,bl1);
                    MMA16816(accV[2*ntp],   al0,al1,al2,al3, bh0,bh1);
                    MMA16816(accV[2*ntp+1], ah0,ah1,ah2,ah3, bh2,bh3);
                    MMA16816(accV[2*ntp+1], ah0,ah1,ah2,ah3, bl2,bl3);
                    MMA16816(accV[2*ntp+1], al0,al1,al2,al3, bh2,bh3);
                }
            }

            #pragma unroll
            for (int nt = 0; nt < 8; nt++){
                const int col = colb + 8*nt + cc;
                float b0 = bias[col],       b1 = bias[col + 1];
                float2 v0; v0.x = accK[nt][0] + b0; v0.y = accK[nt][1] + b1;
                float2 v1; v1.x = accK[nt][2] + b0; v1.y = accK[nt][3] + b1;
                *(float2*)&g_keys[gb + (size_t)r0*128 + col]     = v0;
                *(float2*)&g_keys[gb + (size_t)(r0+8)*128 + col] = v1;
                b0 = bias[128 + col]; b1 = bias[128 + col + 1];
                *(__half2*)&g_vals[gb + (size_t)r0*128 + col]     =
                    __floats2half2_rn(accV[nt][0] + b0, accV[nt][1] + b1);
                *(__half2*)&g_vals[gb + (size_t)(r0+8)*128 + col] =
                    __floats2half2_rn(accV[nt][2] + b0, accV[nt][3] + b1);
            }
        }
    }
}

// ---------------- init: slots <- slots_init, q0, zero accumulators ----------------
__global__ __launch_bounds__(128) void init_q_kernel(
    const float* __restrict__ si,
    const float* __restrict__ Wq, const float* __restrict__ bq,
    const float* __restrict__ gs, const float* __restrict__ bs)
{
    __shared__ float sn[128];
    __shared__ float red[8];
    const int row = blockIdx.x, tid = threadIdx.x;
    const int lane = tid & 31, wrp = tid >> 5;
    float v = si[row*128 + tid];
    g_slots[row*128 + tid] = v;
    g_upd[row*128 + tid] = 0.f;
    if (tid == 0) g_rs[row] = 0.f;
    float s = v, ss = v*v;
    #pragma unroll
    for (int o = 16; o; o >>= 1){
        s  += __shfl_xor_sync(0xffffffffu, s, o);
        ss += __shfl_xor_sync(0xffffffffu, ss, o);
    }
    if (lane == 0){ red[wrp] = s; red[4+wrp] = ss; }
    __syncthreads();
    s  = red[0]+red[1]+red[2]+red[3];
    ss = red[4]+red[5]+red[6]+red[7];
    float m = s*(1.f/128.f);
    float rstd = rsqrtf(ss*(1.f/128.f) - m*m + 1e-5f);
    sn[tid] = (v - m)*rstd*gs[tid] + bs[tid];
    __syncthreads();
    float acc = bq[tid];
    const float4* wr  = (const float4*)(Wq + tid*128);
    const float4* sn4 = (const float4*)sn;
    #pragma unroll
    for (int e = 0; e < 32; e++){
        float4 w = wr[e], q = sn4[e];
        acc += w.x*q.x + w.y*q.y + w.z*q.z + w.w*q.w;
    }
    g_q[row*128 + tid] = acc * SCALE;
}

// ---------------- kernel 3: FUSED logits + softmax + (attn @ V) partials ----------------
// 128 threads, max 4 CTAs/SM (reg cap); grid = B * 32
__global__ __launch_bounds__(128, 4) void fused_attn_upd_kernel()
{
    __shared__ float qp[NS*132];       // q transposed by d-segment, pitch 132
    __shared__ float ps[NS][132];      // softmax probs, padded
    __shared__ float2 redv[NS][64];    // phase-2 cross-half reduction
    const int tid = threadIdx.x;
    const int bb = blockIdx.x >> 5;
    const int n0 = (blockIdx.x & 31) * 128;

    // stage q: qp[seg][i*16 + k] = q[i][seg*16 + k]
    {
        const int sg = tid >> 4, k = tid & 15;
        #pragma unroll
        for (int i = 0; i < 8; i++)
            qp[sg*132 + i*16 + k] = g_q[bb*1024 + i*128 + tid];
    }
    __syncthreads();

    const int seg  = tid & 7;
    const int grp  = tid >> 3;          // 16 groups, each 2 tokens per pass
    const float* qseg = qp + seg*132;
    float srs_acc = 0.f;

    #pragma unroll 1
    for (int pass = 0; pass < 4; pass++){
        const int tok = pass*32 + grp*2;
        const float4* ka = (const float4*)(g_keys + (size_t)(bb*4096 + n0 + tok)*128 + seg*16);
        const float4* kb = (const float4*)((const float*)ka + 128);
        float4 a0 = ka[0], a1 = ka[1], a2 = ka[2], a3 = ka[3];
        float4 b0 = kb[0], b1 = kb[1], b2 = kb[2], b3 = kb[3];
        float la[8], lb[8];
        #pragma unroll
        for (int i = 0; i < 8; i++){
            const float4* q4 = (const float4*)(qseg + i*16);
            float4 q0 = q4[0], q1 = q4[1], q2 = q4[2], q3 = q4[3];
            la[i] = a0.x*q0.x + a0.y*q0.y + a0.z*q0.z + a0.w*q0.w
                  + a1.x*q1.x + a1.y*q1.y + a1.z*q1.z + a1.w*q1.w
                  + a2.x*q2.x + a2.y*q2.y + a2.z*q2.z + a2.w*q2.w
                  + a3.x*q3.x + a3.y*q3.y + a3.z*q3.z + a3.w*q3.w;
            lb[i] = b0.x*q0.x + b0.y*q0.y + b0.z*q0.z + b0.w*q0.w
                  + b1.x*q1.x + b1.y*q1.y + b1.z*q1.z + b1.w*q1.w
                  + b2.x*q2.x + b2.y*q2.y + b2.z*q2.z + b2.w*q2.w
                  + b3.x*q3.x + b3.y*q3.y + b3.z*q3.z + b3.w*q3.w;
        }
        #pragma unroll
        for (int i = 0; i < 8; i++){
            la[i] += __shfl_xor_sync(0xffffffffu, la[i], 1);
            la[i] += __shfl_xor_sync(0xffffffffu, la[i], 2);
            la[i] += __shfl_xor_sync(0xffffffffu, la[i], 4);
            lb[i] += __shfl_xor_sync(0xffffffffu, lb[i], 1);
            lb[i] += __shfl_xor_sync(0xffffffffu, lb[i], 2);
            lb[i] += __shfl_xor_sync(0xffffffffu, lb[i], 4);
        }
        float mxa = la[0], mxb = lb[0];
        #pragma unroll
        for (int i = 1; i < 8; i++){ mxa = fmaxf(mxa, la[i]); mxb = fmaxf(mxb, lb[i]); }
        float ea = __expf(la[seg] - mxa);
        float eb = __expf(lb[seg] - mxb);
        float sa = ea, sbv = eb;
        sa  += __shfl_xor_sync(0xffffffffu, sa, 1);
        sbv += __shfl_xor_sync(0xffffffffu, sbv, 1);
        sa  += __shfl_xor_sync(0xffffffffu, sa, 2);
        sbv += __shfl_xor_sync(0xffffffffu, sbv, 2);
        sa  += __shfl_xor_sync(0xffffffffu, sa, 4);
        sbv += __shfl_xor_sync(0xffffffffu, sbv, 4);
        float pa = ea*(1.f/sa) + 1e-8f;
        float pb = eb*(1.f/sbv) + 1e-8f;
        ps[seg][tok]   = pa;
        ps[seg][tok+1] = pb;
        srs_acc += pa + pb;
    }
    srs_acc += __shfl_xor_sync(0xffffffffu, srs_acc, 8);
    srs_acc += __shfl_xor_sync(0xffffffffu, srs_acc, 16);
    if ((tid & 31) < 8) atomicAdd(&g_rs[bb*8 + seg], srs_acc);
    __syncthreads();

    // ---- phase 2: partial updates = p^T @ V, fp16 vals, half2 per thread ----
    const int half_ = tid >> 6;           // token half
    const int dp    = tid & 63;           // d-pair index (d = 2*dp)
    float2 acc[8];
    #pragma unroll
    for (int i = 0; i < 8; i++){ acc[i].x = 0.f; acc[i].y = 0.f; }
    const __half2* vp = (const __half2*)g_vals
                        + ((size_t)(bb*4096 + n0 + half_*64))*64 + dp;
    #pragma unroll 2
    for (int n = 0; n < 64; n += 4){
        __half2 h0 = vp[(n+0)*64];
        __half2 h1 = vp[(n+1)*64];
        __half2 h2 = vp[(n+2)*64];
        __half2 h3 = vp[(n+3)*64];
        float2 v0 = __half22float2(h0);
        float2 v1 = __half22float2(h1);
        float2 v2 = __half22float2(h2);
        float2 v3 = __half22float2(h3);
        #pragma unroll
        for (int i = 0; i < 8; i++){
            float4 p = *(const float4*)&ps[i][half_*64 + n];
            acc[i].x += p.x*v0.x + p.y*v1.x + p.z*v2.x + p.w*v3.x;
            acc[i].y += p.x*v0.y + p.y*v1.y + p.z*v2.y + p.w*v3.y;
        }
    }
    if (half_){
        #pragma unroll
        for (int i = 0; i < 8; i++) redv[i][dp] = acc[i];
    }
    __syncthreads();
    if (!half_){
        #pragma unroll
        for (int i = 0; i < 8; i++){
            float2 o = redv[i][dp];
            atomicAdd(&g_upd[(bb*8+i)*128 + 2*dp],     acc[i].x + o.x);
            atomicAdd(&g_upd[(bb*8+i)*128 + 2*dp + 1], acc[i].y + o.y);
        }
    }
}

// ---------------- kernel 4: GRU + LN + MLP + next-iter q; 4 rows per block ----------------
__global__ __launch_bounds__(128) void gru_mlp_q_kernel(
    const float* __restrict__ W_ih, const float* __restrict__ W_hh,
    const float* __restrict__ b_ih, const float* __restrict__ b_hh,
    const float* __restrict__ gm, const float* __restrict__ bm,
    const float* __restrict__ W1, const float* __restrict__ b1,
    const float* __restrict__ W2, const float* __restrict__ b2,
    const float* __restrict__ Wq, const float* __restrict__ bq,
    const float* __restrict__ gs, const float* __restrict__ bs)
{
    __shared__ float sa[4][128], sb[4][128], sc[4][128];
    __shared__ float red_s[4][4], red_ss[4][4];
    const int tid = threadIdx.x;
    const int lane = tid & 31, wrp = tid >> 5;
    const int r0 = blockIdx.x * 4;

    float hv[4], uv[4], rsv[4];
    #pragma unroll
    for (int j = 0; j < 4; j++){
        const int row = r0 + j;
        rsv[j] = g_rs[row];
        uv[j]  = g_upd[row*128 + tid];
        hv[j]  = g_slots[row*128 + tid];
    }
    __syncthreads();   // all reads complete before any thread zeroes
    #pragma unroll
    for (int j = 0; j < 4; j++){
        const int row = r0 + j;
        sa[j][tid] = uv[j] / rsv[j];
        sb[j][tid] = hv[j];
        g_upd[row*128 + tid] = 0.f;
    }
    if (tid < 4) g_rs[r0 + tid] = 0.f;
    __syncthreads();

    float gi[3][4], gh[3][4];
    #pragma unroll 1
    for (int g = 0; g < 3; g++){
        const float4* wi = (const float4*)(W_ih + (g*128 + tid)*128);
        const float4* wh = (const float4*)(W_hh + (g*128 + tid)*128);
        const float bi = b_ih[g*128 + tid], bh = b_hh[g*128 + tid];
        float ai[4], ah[4];
        #pragma unroll
        for (int j = 0; j < 4; j++){ ai[j] = bi; ah[j] = bh; }
        #pragma unroll 4
        for (int e = 0; e < 32; e++){
            float4 w = wi[e];
            #pragma unroll
            for (int j = 0; j < 4; j++){
                float4 uu = ((const float4*)sa[j])[e];
                ai[j] += w.x*uu.x + w.y*uu.y + w.z*uu.z + w.w*uu.w;
            }
            float4 c = wh[e];
            #pragma unroll
            for (int j = 0; j < 4; j++){
                float4 pp = ((const float4*)sb[j])[e];
                ah[j] += c.x*pp.x + c.y*pp.y + c.z*pp.z + c.w*pp.w;
            }
        }
        #pragma unroll
        for (int j = 0; j < 4; j++){ gi[g][j] = ai[j]; gh[g][j] = ah[j]; }
    }

    float hnv[4];
    #pragma unroll
    for (int j = 0; j < 4; j++){
        float r = 1.f/(1.f + __expf(-(gi[0][j]+gh[0][j])));
        float z = 1.f/(1.f + __expf(-(gi[1][j]+gh[1][j])));
        float n = tanhf(gi[2][j] + r*gh[2][j]);
        hnv[j] = (1.f - z)*n + z*hv[j];
    }

    #pragma unroll
    for (int j = 0; j < 4; j++){
        float s = hnv[j], ss = hnv[j]*hnv[j];
        #pragma unroll
        for (int o = 16; o; o >>= 1){
            s  += __shfl_xor_sync(0xffffffffu, s, o);
            ss += __shfl_xor_sync(0xffffffffu, ss, o);
        }
        if (lane == 0){ red_s[wrp][j] = s; red_ss[wrp][j] = ss; }
    }
    __syncthreads();
    #pragma unroll
    for (int j = 0; j < 4; j++){
        float s  = red_s[0][j]+red_s[1][j]+red_s[2][j]+red_s[3][j];
        float ss = red_ss[0][j]+red_ss[1][j]+red_ss[2][j]+red_ss[3][j];
        float m = s*(1.f/128.f);
        float rstd = rsqrtf(ss*(1.f/128.f) - m*m + 1e-5f);
        sc[j][tid] = (hnv[j] - m)*rstd*gm[tid] + bm[tid];
    }
    __syncthreads();

    {
        const float4* w1 = (const float4*)(W1 + tid*128);
        const float bb1 = b1[tid];
        float hid[4];
        #pragma unroll
        for (int j = 0; j < 4; j++) hid[j] = bb1;
        #pragma unroll 4
        for (int e = 0; e < 32; e++){
            float4 w = w1[e];
            #pragma unroll
            for (int j = 0; j < 4; j++){
                float4 xx = ((const float4*)sc[j])[e];
                hid[j] += w.x*xx.x + w.y*xx.y + w.z*xx.z + w.w*xx.w;
            }
        }
        #pragma unroll
        for (int j = 0; j < 4; j++) sa[j][tid] = fmaxf(hid[j], 0.f);
    }
    __syncthreads();

    float outv[4];
    {
        const float4* w2 = (const float4*)(W2 + tid*128);
        const float bb2 = b2[tid];
        #pragma unroll
        for (int j = 0; j < 4; j++) outv[j] = hnv[j] + bb2;
        #pragma unroll 4
        for (int e = 0; e < 32; e++){
            float4 w = w2[e];
            #pragma unroll
            for (int j = 0; j < 4; j++){
                float4 xx = ((const float4*)sa[j])[e];
                outv[j] += w.x*xx.x + w.y*xx.y + w.z*xx.z + w.w*xx.w;
            }
        }
    }
    #pragma unroll
    for (int j = 0; j < 4; j++)
        g_slots[(r0+j)*128 + tid] = outv[j];
    __syncthreads();

    #pragma unroll
    for (int j = 0; j < 4; j++){
        float s = outv[j], ss = outv[j]*outv[j];
        #pragma unroll
        for (int o = 16; o; o >>= 1){
            s  += __shfl_xor_sync(0xffffffffu, s, o);
            ss += __shfl_xor_sync(0xffffffffu, ss, o);
        }
        if (lane == 0){ red_s[wrp][j] = s; red_ss[wrp][j] = ss; }
    }
    __syncthreads();
    #pragma unroll
    for (int j = 0; j < 4; j++){
        float s  = red_s[0][j]+red_s[1][j]+red_s[2][j]+red_s[3][j];
        float ss = red_ss[0][j]+red_ss[1][j]+red_ss[2][j]+red_ss[3][j];
        float m = s*(1.f/128.f);
        float rstd = rsqrtf(ss*(1.f/128.f) - m*m + 1e-5f);
        sb[j][tid] = (outv[j] - m)*rstd*gs[tid] + bs[tid];
    }
    __syncthreads();
    {
        const float4* wq = (const float4*)(Wq + tid*128);
        const float bbq = bq[tid];
        float qa[4];
        #pragma unroll
        for (int j = 0; j < 4; j++) qa[j] = bbq;
        #pragma unroll 4
        for (int e = 0; e < 32; e++){
            float4 w = wq[e];
            #pragma unroll
            for (int j = 0; j < 4; j++){
                float4 xx = ((const float4*)sb[j])[e];
                qa[j] += w.x*xx.x + w.y*xx.y + w.z*xx.z + w.w*xx.w;
            }
        }
        #pragma unroll
        for (int j = 0; j < 4; j++)
            g_q[(r0+j)*128 + tid] = qa[j] * SCALE;
    }
}

// ---------------- launch ----------------
extern "C" void kernel_launch(void* const* d_in, const int* in_sizes, int n_in,
                              void* d_out, int out_size)
{
    const float* x    = (const float*)d_in[0];
    const float* si   = (const float*)d_in[1];
    const float* Wq   = (const float*)d_in[2];
    const float* bq   = (const float*)d_in[3];
    const float* Wk   = (const float*)d_in[4];
    const float* bk   = (const float*)d_in[5];
    const float* Wv   = (const float*)d_in[6];
    const float* bv   = (const float*)d_in[7];
    const float* gin  = (const float*)d_in[8];
    const float* bin  = (const float*)d_in[9];
    const float* gsl  = (const float*)d_in[10];
    const float* bsl  = (const float*)d_in[11];
    const float* gm   = (const float*)d_in[12];
    const float* bm   = (const float*)d_in[13];
    const float* W1   = (const float*)d_in[14];
    const float* b1   = (const float*)d_in[15];
    const float* W2   = (const float*)d_in[16];
    const float* b2   = (const float*)d_in[17];
    const float* W_ih = (const float*)d_in[18];
    const float* W_hh = (const float*)d_in[19];
    const float* b_ih = (const float*)d_in[20];
    const float* b_hh = (const float*)d_in[21];

    static bool attr_set = false;
    if (!attr_set){
        cudaFuncSetAttribute(ln_kv_mma_kernel,
                             cudaFuncAttributeMaxDynamicSharedMemorySize, S_TOTAL);
        attr_set = true;
    }

    prep_w_kernel<<<128, 256>>>(Wk, Wv);
    init_q_kernel<<<512, 128>>>(si, Wq, bq, gsl, bsl);
    ln_kv_mma_kernel<<<1024, 256, S_TOTAL>>>(x, bk, bv, gin, bin);
    for (int it = 0; it < 3; it++){
        fused_attn_upd_kernel<<<2048, 128>>>();
        gru_mlp_q_kernel<<<128, 128>>>(W_ih, W_hh, b_ih, b_hh, gm, bm,
                                       W1, b1, W2, b2, Wq, bq, gsl, bsl);
    }
    export_kernel<<<256, 256>>>((float*)d_out);
}

// round 8
// speedup vs baseline: 1.4435x; 1.4435x over previous
#include <cuda_runtime.h>
#include <cuda_fp16.h>
#include <cstdint>

#define BB 64
#define NN 4096
#define DD 128
#define NS 8
#define SCALE 0.08838834764831845f

// ---------------- device scratch ----------------
__device__ __half g_xn[BB*NN*DD];     // 67 MB fp16 normalized input
__device__ float g_qk[BB*NS*DD];      // (SCALE*q) @ Wk
__device__ float g_lb[BB*NS];         // (SCALE*q) . bk  (logit bias)
__device__ float g_slots[BB*NS*DD];
__device__ float g_y[BB*NS*DD];       // attn @ xn accumulators (unnormalized)
__device__ float g_rs[BB*NS];         // rowsum accumulators
__device__ float g_wkT[DD*DD];        // Wk transposed: wkT[d][j] = Wk[j][d]

__global__ __launch_bounds__(256) void export_kernel(float* __restrict__ dst){
    int i = blockIdx.x*256 + threadIdx.x;
    dst[i] = g_slots[i];
}

__global__ __launch_bounds__(256) void prep_wkT_kernel(const float* __restrict__ Wk){
    int i = blockIdx.x*256 + threadIdx.x;     // 0..16383
    int d = i >> 7, j = i & 127;
    g_wkT[d*128 + j] = Wk[j*128 + d];
}

// ---------------- kernel 1: xn = LN(x), stored fp16 ----------------
// grid 2048, 256 threads; 128 rows per block, 2 threads per row
__global__ __launch_bounds__(256) void ln_x_kernel(
    const float* __restrict__ x,
    const float* __restrict__ gin, const float* __restrict__ bin)
{
    const int tid = threadIdx.x;
    const int row = blockIdx.x*128 + (tid >> 1);
    const int half_ = tid & 1;
    const float* xr = x + (size_t)row*128 + half_*64;
    float4 v[16];
    float s = 0.f, ss = 0.f;
    #pragma unroll
    for (int j = 0; j < 16; j++){
        v[j] = ((const float4*)xr)[j];
        s  += v[j].x + v[j].y + v[j].z + v[j].w;
        ss += v[j].x*v[j].x + v[j].y*v[j].y + v[j].z*v[j].z + v[j].w*v[j].w;
    }
    s  += __shfl_xor_sync(0xffffffffu, s, 1);
    ss += __shfl_xor_sync(0xffffffffu, ss, 1);
    const float m = s * (1.f/128.f);
    const float rstd = rsqrtf(ss*(1.f/128.f) - m*m + 1e-5f);
    __half* out = g_xn + (size_t)row*128 + half_*64;
    #pragma unroll
    for (int j = 0; j < 16; j++){
        const int k0 = half_*64 + j*4;
        float4 g4 = ((const float4*)gin)[k0>>2];
        float4 b4 = ((const float4*)bin)[k0>>2];
        float n0 = (v[j].x - m)*rstd*g4.x + b4.x;
        float n1 = (v[j].y - m)*rstd*g4.y + b4.y;
        float n2 = (v[j].z - m)*rstd*g4.z + b4.z;
        float n3 = (v[j].w - m)*rstd*g4.w + b4.w;
        *(__half2*)(out + j*4)     = __floats2half2_rn(n0, n1);
        *(__half2*)(out + j*4 + 2) = __floats2half2_rn(n2, n3);
    }
}

// ---------------- init: slots, zero accums, qk0 + lb0 ----------------
// grid 512 (one slot-row per block), 128 threads
__global__ __launch_bounds__(128) void init_q_kernel(
    const float* __restrict__ si,
    const float* __restrict__ Wq, const float* __restrict__ bq,
    const float* __restrict__ gs, const float* __restrict__ bs,
    const float* __restrict__ bk)
{
    __shared__ float sn[128];
    __shared__ float sq[128];
    __shared__ float red[8];
    const int row = blockIdx.x, tid = threadIdx.x;
    const int lane = tid & 31, wrp = tid >> 5;
    float v = si[row*128 + tid];
    g_slots[row*128 + tid] = v;
    g_y[row*128 + tid] = 0.f;
    if (tid == 0) g_rs[row] = 0.f;
    float s = v, ss = v*v;
    #pragma unroll
    for (int o = 16; o; o >>= 1){
        s  += __shfl_xor_sync(0xffffffffu, s, o);
        ss += __shfl_xor_sync(0xffffffffu, ss, o);
    }
    if (lane == 0){ red[wrp] = s; red[4+wrp] = ss; }
    __syncthreads();
    s  = red[0]+red[1]+red[2]+red[3];
    ss = red[4]+red[5]+red[6]+red[7];
    float m = s*(1.f/128.f);
    float rstd = rsqrtf(ss*(1.f/128.f) - m*m + 1e-5f);
    sn[tid] = (v - m)*rstd*gs[tid] + bs[tid];
    __syncthreads();
    float acc = bq[tid];
    {
        const float4* wr  = (const float4*)(Wq + tid*128);
        const float4* sn4 = (const float4*)sn;
        #pragma unroll
        for (int e = 0; e < 32; e++){
            float4 w = wr[e], q = sn4[e];
            acc += w.x*q.x + w.y*q.y + w.z*q.z + w.w*q.w;
        }
    }
    sq[tid] = acc * SCALE;
    __syncthreads();
    // qk = sq @ Wk  (via WkT rows)
    float qk = 0.f;
    {
        const float4* wr  = (const float4*)(g_wkT + tid*128);
        const float4* sq4 = (const float4*)sq;
        #pragma unroll
        for (int e = 0; e < 32; e++){
            float4 w = wr[e], q = sq4[e];
            qk += w.x*q.x + w.y*q.y + w.z*q.z + w.w*q.w;
        }
    }
    g_qk[row*128 + tid] = qk;
    // lbias = sq . bk
    float p = sq[tid] * bk[tid];
    #pragma unroll
    for (int o = 16; o; o >>= 1) p += __shfl_xor_sync(0xffffffffu, p, o);
    __syncthreads();
    if (lane == 0) red[wrp] = p;
    __syncthreads();
    if (tid == 0) g_lb[row] = red[0]+red[1]+red[2]+red[3];
}

__device__ __forceinline__ void cvt8(uint4 u, float* f){
    const __half2* h = (const __half2*)&u;
    float2 a = __half22float2(h[0]); f[0]=a.x; f[1]=a.y;
    float2 b = __half22float2(h[1]); f[2]=b.x; f[3]=b.y;
    float2 c = __half22float2(h[2]); f[4]=c.x; f[5]=c.y;
    float2 d = __half22float2(h[3]); f[6]=d.x; f[7]=d.y;
}

// ---------------- kernel 3: FUSED logits + softmax + y partials ----------------
// 128 threads; 8 lanes per token; 2 tokens/group/pass; grid = B * 32
__global__ __launch_bounds__(128) void fused_attn_upd_kernel()
{
    __shared__ float qp[NS*132];       // qk transposed by d-segment, pitch 132
    __shared__ float ps[NS][132];      // softmax probs, padded
    __shared__ float lbs[NS];
    __shared__ float2 redv[NS][64];
    const int tid = threadIdx.x;
    const int bb = blockIdx.x >> 5;
    const int n0 = (blockIdx.x & 31) * 128;

    {
        const int sg = tid >> 4, k = tid & 15;
        #pragma unroll
        for (int i = 0; i < 8; i++)
            qp[sg*132 + i*16 + k] = g_qk[bb*1024 + i*128 + tid];
    }
    if (tid < 8) lbs[tid] = g_lb[bb*8 + tid];
    __syncthreads();

    const int seg  = tid & 7;
    const int grp  = tid >> 3;
    const float* qseg = qp + seg*132;
    float srs_acc = 0.f;

    #pragma unroll 1
    for (int pass = 0; pass < 4; pass++){
        const int tok = pass*32 + grp*2;
        const __half* xr = g_xn + (size_t)(bb*4096 + n0 + tok)*128 + seg*16;
        uint4 A0 = *(const uint4*)xr;
        uint4 A1 = *(const uint4*)(xr + 8);
        uint4 B0 = *(const uint4*)(xr + 128);
        uint4 B1 = *(const uint4*)(xr + 136);
        float aF[16], bF[16];
        cvt8(A0, aF); cvt8(A1, aF+8);
        cvt8(B0, bF); cvt8(B1, bF+8);

        float la[8], lb_[8];
        #pragma unroll
        for (int i = 0; i < 8; i++){
            const float* qq = qseg + i*16;
            float s0 = 0.f, s1 = 0.f;
            #pragma unroll
            for (int k = 0; k < 16; k++){
                s0 += aF[k]*qq[k];
                s1 += bF[k]*qq[k];
            }
            la[i] = s0; lb_[i] = s1;
        }
        #pragma unroll
        for (int i = 0; i < 8; i++){
            la[i]  += __shfl_xor_sync(0xffffffffu, la[i], 1);
            la[i]  += __shfl_xor_sync(0xffffffffu, la[i], 2);
            la[i]  += __shfl_xor_sync(0xffffffffu, la[i], 4);
            lb_[i] += __shfl_xor_sync(0xffffffffu, lb_[i], 1);
            lb_[i] += __shfl_xor_sync(0xffffffffu, lb_[i], 2);
            lb_[i] += __shfl_xor_sync(0xffffffffu, lb_[i], 4);
            la[i]  += lbs[i];
            lb_[i] += lbs[i];
        }
        float mxa = la[0], mxb = lb_[0];
        #pragma unroll
        for (int i = 1; i < 8; i++){ mxa = fmaxf(mxa, la[i]); mxb = fmaxf(mxb, lb_[i]); }
        float ea = __expf(la[seg]  - mxa);
        float eb = __expf(lb_[seg] - mxb);
        float sa = ea, sbv = eb;
        sa  += __shfl_xor_sync(0xffffffffu, sa, 1);
        sbv += __shfl_xor_sync(0xffffffffu, sbv, 1);
        sa  += __shfl_xor_sync(0xffffffffu, sa, 2);
        sbv += __shfl_xor_sync(0xffffffffu, sbv, 2);
        sa  += __shfl_xor_sync(0xffffffffu, sa, 4);
        sbv += __shfl_xor_sync(0xffffffffu, sbv, 4);
        float pa = ea*(1.f/sa)  + 1e-8f;
        float pb = eb*(1.f/sbv) + 1e-8f;
        ps[seg][tok]   = pa;
        ps[seg][tok+1] = pb;
        srs_acc += pa + pb;
    }
    srs_acc += __shfl_xor_sync(0xffffffffu, srs_acc, 8);
    srs_acc += __shfl_xor_sync(0xffffffffu, srs_acc, 16);
    if ((tid & 31) < 8) atomicAdd(&g_rs[bb*8 + seg], srs_acc);
    __syncthreads();

    // ---- phase 2: y partials = p^T @ xn (fp16), half2 per thread ----
    const int half_ = tid >> 6;
    const int dp    = tid & 63;
    float2 acc[8];
    #pragma unroll
    for (int i = 0; i < 8; i++){ acc[i].x = 0.f; acc[i].y = 0.f; }
    const __half2* vp = (const __half2*)g_xn
                        + ((size_t)(bb*4096 + n0 + half_*64))*64 + dp;
    #pragma unroll 2
    for (int n = 0; n < 64; n += 4){
        float2 v0 = __half22float2(vp[(n+0)*64]);
        float2 v1 = __half22float2(vp[(n+1)*64]);
        float2 v2 = __half22float2(vp[(n+2)*64]);
        float2 v3 = __half22float2(vp[(n+3)*64]);
        #pragma unroll
        for (int i = 0; i < 8; i++){
            float4 p = *(const float4*)&ps[i][half_*64 + n];
            acc[i].x += p.x*v0.x + p.y*v1.x + p.z*v2.x + p.w*v3.x;
            acc[i].y += p.x*v0.y + p.y*v1.y + p.z*v2.y + p.w*v3.y;
        }
    }
    if (half_){
        #pragma unroll
        for (int i = 0; i < 8; i++) redv[i][dp] = acc[i];
    }
    __syncthreads();
    if (!half_){
        #pragma unroll
        for (int i = 0; i < 8; i++){
            float2 o = redv[i][dp];
            atomicAdd(&g_y[(bb*8+i)*128 + 2*dp],     acc[i].x + o.x);
            atomicAdd(&g_y[(bb*8+i)*128 + 2*dp + 1], acc[i].y + o.y);
        }
    }
}

// ---------------- kernel 4: Wv·y + GRU + LN + MLP + next qk/lb; 4 rows/block ----------------
__global__ __launch_bounds__(128) void gru_mlp_q_kernel(
    const float* __restrict__ W_ih, const float* __restrict__ W_hh,
    const float* __restrict__ b_ih, const float* __restrict__ b_hh,
    const float* __restrict__ gm, const float* __restrict__ bm,
    const float* __restrict__ W1, const float* __restrict__ b1,
    const float* __restrict__ W2, const float* __restrict__ b2,
    const float* __restrict__ Wq, const float* __restrict__ bq,
    const float* __restrict__ gs, const float* __restrict__ bs,
    const float* __restrict__ Wv, const float* __restrict__ bv,
    const float* __restrict__ bk)
{
    __shared__ float sa[4][128], sb[4][128], sc[4][128], sy[4][128];
    __shared__ float red_s[4][4], red_ss[4][4];
    const int tid = threadIdx.x;
    const int lane = tid & 31, wrp = tid >> 5;
    const int r0 = blockIdx.x * 4;

    float hv[4], yv[4], rsv[4];
    #pragma unroll
    for (int j = 0; j < 4; j++){
        const int row = r0 + j;
        rsv[j] = g_rs[row];
        yv[j]  = g_y[row*128 + tid];
        hv[j]  = g_slots[row*128 + tid];
    }
    __syncthreads();   // all reads complete before zeroing
    #pragma unroll
    for (int j = 0; j < 4; j++){
        sy[j][tid] = yv[j] / rsv[j];
        g_y[(r0+j)*128 + tid] = 0.f;
    }
    if (tid < 4) g_rs[r0 + tid] = 0.f;
    __syncthreads();

    // updates u = Wv @ (y/rs) + bv
    {
        const float4* wv = (const float4*)(Wv + tid*128);
        const float bvv = bv[tid];
        float uu[4] = {bvv, bvv, bvv, bvv};
        #pragma unroll 4
        for (int e = 0; e < 32; e++){
            float4 w = wv[e];
            #pragma unroll
            for (int j = 0; j < 4; j++){
                float4 x4 = ((const float4*)sy[j])[e];
                uu[j] += w.x*x4.x + w.y*x4.y + w.z*x4.z + w.w*x4.w;
            }
        }
        #pragma unroll
        for (int j = 0; j < 4; j++){ sa[j][tid] = uu[j]; sb[j][tid] = hv[j]; }
    }
    __syncthreads();

    float gi[3][4], gh[3][4];
    #pragma unroll 1
    for (int g = 0; g < 3; g++){
        const float4* wi = (const float4*)(W_ih + (g*128 + tid)*128);
        const float4* wh = (const float4*)(W_hh + (g*128 + tid)*128);
        const float bi = b_ih[g*128 + tid], bh = b_hh[g*128 + tid];
        float ai[4], ah[4];
        #pragma unroll
        for (int j = 0; j < 4; j++){ ai[j] = bi; ah[j] = bh; }
        #pragma unroll 4
        for (int e = 0; e < 32; e++){
            float4 w = wi[e];
            #pragma unroll
            for (int j = 0; j < 4; j++){
                float4 uu = ((const float4*)sa[j])[e];
                ai[j] += w.x*uu.x + w.y*uu.y + w.z*uu.z + w.w*uu.w;
            }
            float4 c = wh[e];
            #pragma unroll
            for (int j = 0; j < 4; j++){
                float4 pp = ((const float4*)sb[j])[e];
                ah[j] += c.x*pp.x + c.y*pp.y + c.z*pp.z + c.w*pp.w;
            }
        }
        #pragma unroll
        for (int j = 0; j < 4; j++){ gi[g][j] = ai[j]; gh[g][j] = ah[j]; }
    }

    float hnv[4];
    #pragma unroll
    for (int j = 0; j < 4; j++){
        float r = 1.f/(1.f + __expf(-(gi[0][j]+gh[0][j])));
        float z = 1.f/(1.f + __expf(-(gi[1][j]+gh[1][j])));
        float n = tanhf(gi[2][j] + r*gh[2][j]);
        hnv[j] = (1.f - z)*n + z*hv[j];
    }

    // LN(hn) -> sc
    #pragma unroll
    for (int j = 0; j < 4; j++){
        float s = hnv[j], ss = hnv[j]*hnv[j];
        #pragma unroll
        for (int o = 16; o; o >>= 1){
            s  += __shfl_xor_sync(0xffffffffu, s, o);
            ss += __shfl_xor_sync(0xffffffffu, ss, o);
        }
        if (lane == 0){ red_s[wrp][j] = s; red_ss[wrp][j] = ss; }
    }
    __syncthreads();
    #pragma unroll
    for (int j = 0; j < 4; j++){
        float s  = red_s[0][j]+red_s[1][j]+red_s[2][j]+red_s[3][j];
        float ss = red_ss[0][j]+red_ss[1][j]+red_ss[2][j]+red_ss[3][j];
        float m = s*(1.f/128.f);
        float rstd = rsqrtf(ss*(1.f/128.f) - m*m + 1e-5f);
        sc[j][tid] = (hnv[j] - m)*rstd*gm[tid] + bm[tid];
    }
    __syncthreads();

    // MLP layer 1 (relu) -> sa
    {
        const float4* w1 = (const float4*)(W1 + tid*128);
        const float bb1 = b1[tid];
        float hid[4];
        #pragma unroll
        for (int j = 0; j < 4; j++) hid[j] = bb1;
        #pragma unroll 4
        for (int e = 0; e < 32; e++){
            float4 w = w1[e];
            #pragma unroll
            for (int j = 0; j < 4; j++){
                float4 xx = ((const float4*)sc[j])[e];
                hid[j] += w.x*xx.x + w.y*xx.y + w.z*xx.z + w.w*xx.w;
            }
        }
        #pragma unroll
        for (int j = 0; j < 4; j++) sa[j][tid] = fmaxf(hid[j], 0.f);
    }
    __syncthreads();

    // MLP layer 2 -> out (residual)
    float outv[4];
    {
        const float4* w2 = (const float4*)(W2 + tid*128);
        const float bb2 = b2[tid];
        #pragma unroll
        for (int j = 0; j < 4; j++) outv[j] = hnv[j] + bb2;
        #pragma unroll 4
        for (int e = 0; e < 32; e++){
            float4 w = w2[e];
            #pragma unroll
            for (int j = 0; j < 4; j++){
                float4 xx = ((const float4*)sa[j])[e];
                outv[j] += w.x*xx.x + w.y*xx.y + w.z*xx.z + w.w*xx.w;
            }
        }
    }
    #pragma unroll
    for (int j = 0; j < 4; j++)
        g_slots[(r0+j)*128 + tid] = outv[j];
    __syncthreads();

    // LN(out) -> sb, then q projection
    #pragma unroll
    for (int j = 0; j < 4; j++){
        float s = outv[j], ss = outv[j]*outv[j];
        #pragma unroll
        for (int o = 16; o; o >>= 1){
            s  += __shfl_xor_sync(0xffffffffu, s, o);
            ss += __shfl_xor_sync(0xffffffffu, ss, o);
        }
        if (lane == 0){ red_s[wrp][j] = s; red_ss[wrp][j] = ss; }
    }
    __syncthreads();
    #pragma unroll
    for (int j = 0; j < 4; j++){
        float s  = red_s[0][j]+red_s[1][j]+red_s[2][j]+red_s[3][j];
        float ss = red_ss[0][j]+red_ss[1][j]+red_ss[2][j]+red_ss[3][j];
        float m = s*(1.f/128.f);
        float rstd = rsqrtf(ss*(1.f/128.f) - m*m + 1e-5f);
        sb[j][tid] = (outv[j] - m)*rstd*gs[tid] + bs[tid];
    }
    __syncthreads();
    float qa[4];
    {
        const float4* wq = (const float4*)(Wq + tid*128);
        const float bbq = bq[tid];
        #pragma unroll
        for (int j = 0; j < 4; j++) qa[j] = bbq;
        #pragma unroll 4
        for (int e = 0; e < 32; e++){
            float4 w = wq[e];
            #pragma unroll
            for (int j = 0; j < 4; j++){
                float4 xx = ((const float4*)sb[j])[e];
                qa[j] += w.x*xx.x + w.y*xx.y + w.z*xx.z + w.w*xx.w;
            }
        }
    }
    // stage scaled q in sc (free), compute qk + lbias
    #pragma unroll
    for (int j = 0; j < 4; j++) sc[j][tid] = qa[j] * SCALE;
    __syncthreads();
    {
        const float4* wkt = (const float4*)(g_wkT + tid*128);
        float qk[4] = {0.f, 0.f, 0.f, 0.f};
        #pragma unroll 4
        for (int e = 0; e < 32; e++){
            float4 w = wkt[e];
            #pragma unroll
            for (int j = 0; j < 4; j++){
                float4 xx = ((const float4*)sc[j])[e];
                qk[j] += w.x*xx.x + w.y*xx.y + w.z*xx.z + w.w*xx.w;
            }
        }
        #pragma unroll
        for (int j = 0; j < 4; j++)
            g_qk[(r0+j)*128 + tid] = qk[j];
    }
    {
        const float bkv = bk[tid];
        #pragma unroll
        for (int j = 0; j < 4; j++){
            float p = sc[j][tid] * bkv;
            #pragma unroll
            for (int o = 16; o; o >>= 1) p += __shfl_xor_sync(0xffffffffu, p, o);
            if (lane == 0) red_s[wrp][j] = p;
        }
    }
    __syncthreads();
    if (tid < 4)
        g_lb[r0 + tid] = red_s[0][tid]+red_s[1][tid]+red_s[2][tid]+red_s[3][tid];
}

// ---------------- launch ----------------
extern "C" void kernel_launch(void* const* d_in, const int* in_sizes, int n_in,
                              void* d_out, int out_size)
{
    const float* x    = (const float*)d_in[0];
    const float* si   = (const float*)d_in[1];
    const float* Wq   = (const float*)d_in[2];
    const float* bq   = (const float*)d_in[3];
    const float* Wk   = (const float*)d_in[4];
    const float* bk   = (const float*)d_in[5];
    const float* Wv   = (const float*)d_in[6];
    const float* bv   = (const float*)d_in[7];
    const float* gin  = (const float*)d_in[8];
    const float* bin  = (const float*)d_in[9];
    const float* gsl  = (const float*)d_in[10];
    const float* bsl  = (const float*)d_in[11];
    const float* gm   = (const float*)d_in[12];
    const float* bm   = (const float*)d_in[13];
    const float* W1   = (const float*)d_in[14];
    const float* b1   = (const float*)d_in[15];
    const float* W2   = (const float*)d_in[16];
    const float* b2   = (const float*)d_in[17];
    const float* W_ih = (const float*)d_in[18];
    const float* W_hh = (const float*)d_in[19];
    const float* b_ih = (const float*)d_in[20];
    const float* b_hh = (const float*)d_in[21];

    prep_wkT_kernel<<<64, 256>>>(Wk);
    ln_x_kernel<<<2048, 256>>>(x, gin, bin);
    init_q_kernel<<<512, 128>>>(si, Wq, bq, gsl, bsl, bk);
    for (int it = 0; it < 3; it++){
        fused_attn_upd_kernel<<<2048, 128>>>();
        gru_mlp_q_kernel<<<128, 128>>>(W_ih, W_hh, b_ih, b_hh, gm, bm,
                                       W1, b1, W2, b2, Wq, bq, gsl, bsl,
                                       Wv, bv, bk);
    }
    export_kernel<<<256, 256>>>((float*)d_out);
}

// round 9
// speedup vs baseline: 1.8072x; 1.2519x over previous
#include <cuda_runtime.h>
#include <cuda_fp16.h>
#include <cstdint>

#define BB 64
#define NN 4096
#define DD 128
#define NS 8
#define SCALE 0.08838834764831845f

// ---------------- device scratch ----------------
__device__ __half g_xn[BB*NN*DD];     // 67 MB fp16 normalized input
__device__ float g_qk[BB*NS*DD];      // (SCALE*q) @ Wk
__device__ float g_lb[BB*NS];         // (SCALE*q) . bk
__device__ float g_slots[BB*NS*DD];
__device__ float g_y[BB*NS*DD];       // attn @ xn accumulators (unnormalized)
__device__ float g_rs[BB*NS];         // rowsum accumulators
__device__ float g_wkT[DD*DD];

__device__ __forceinline__ uint32_t smem_u32(const void* p){
    uint32_t a;
    asm("{ .reg .u64 t; cvta.to.shared.u64 t, %1; cvt.u32.u64 %0, t; }" : "=r"(a) : "l"(p));
    return a;
}
#define LDSM4(r0,r1,r2,r3,addr) \
    asm volatile("ldmatrix.sync.aligned.m8n8.x4.shared.b16 {%0,%1,%2,%3}, [%4];" \
        : "=r"(r0),"=r"(r1),"=r"(r2),"=r"(r3) : "r"(addr))
#define LDSM2(r0,r1,addr) \
    asm volatile("ldmatrix.sync.aligned.m8n8.x2.shared.b16 {%0,%1}, [%2];" \
        : "=r"(r0),"=r"(r1) : "r"(addr))
#define LDSM2T(r0,r1,addr) \
    asm volatile("ldmatrix.sync.aligned.m8n8.x2.trans.shared.b16 {%0,%1}, [%2];" \
        : "=r"(r0),"=r"(r1) : "r"(addr))
#define MMAF16(c,a0,a1,a2,a3,b0,b1) \
    asm volatile("mma.sync.aligned.m16n8k16.row.col.f32.f16.f16.f32 " \
        "{%0,%1,%2,%3}, {%4,%5,%6,%7}, {%8,%9}, {%0,%1,%2,%3};" \
        : "+f"((c)[0]),"+f"((c)[1]),"+f"((c)[2]),"+f"((c)[3]) \
        : "r"(a0),"r"(a1),"r"(a2),"r"(a3),"r"(b0),"r"(b1))

// smem layout (bytes)
#define SM_QKHI 0
#define SM_QKLO 2176
#define SM_LB   4352
#define SM_LG   4384                   // 256 x 10 floats
#define SM_PA   14624                  // 16 x 264 halfs (pitch 528B)
#define SM_XN   23072                  // 256 x 136 halfs (pitch 272B)
#define SM_TOT  92704

__global__ __launch_bounds__(256) void export_kernel(float* __restrict__ dst){
    int i = blockIdx.x*256 + threadIdx.x;
    dst[i] = g_slots[i];
}
__global__ __launch_bounds__(256) void prep_wkT_kernel(const float* __restrict__ Wk){
    int i = blockIdx.x*256 + threadIdx.x;
    int d = i >> 7, j = i & 127;
    g_wkT[d*128 + j] = Wk[j*128 + d];
}

// ---------------- kernel 1: xn = LN(x), stored fp16 ----------------
__global__ __launch_bounds__(256) void ln_x_kernel(
    const float* __restrict__ x,
    const float* __restrict__ gin, const float* __restrict__ bin)
{
    const int tid = threadIdx.x;
    const int row = blockIdx.x*128 + (tid >> 1);
    const int half_ = tid & 1;
    const float* xr = x + (size_t)row*128 + half_*64;
    float4 v[16];
    float s = 0.f, ss = 0.f;
    #pragma unroll
    for (int j = 0; j < 16; j++){
        v[j] = ((const float4*)xr)[j];
        s  += v[j].x + v[j].y + v[j].z + v[j].w;
        ss += v[j].x*v[j].x + v[j].y*v[j].y + v[j].z*v[j].z + v[j].w*v[j].w;
    }
    s  += __shfl_xor_sync(0xffffffffu, s, 1);
    ss += __shfl_xor_sync(0xffffffffu, ss, 1);
    const float m = s * (1.f/128.f);
    const float rstd = rsqrtf(ss*(1.f/128.f) - m*m + 1e-5f);
    __half* out = g_xn + (size_t)row*128 + half_*64;
    #pragma unroll
    for (int j = 0; j < 16; j++){
        const int k0 = half_*64 + j*4;
        float4 g4 = ((const float4*)gin)[k0>>2];
        float4 b4 = ((const float4*)bin)[k0>>2];
        float n0 = (v[j].x - m)*rstd*g4.x + b4.x;
        float n1 = (v[j].y - m)*rstd*g4.y + b4.y;
        float n2 = (v[j].z - m)*rstd*g4.z + b4.z;
        float n3 = (v[j].w - m)*rstd*g4.w + b4.w;
        *(__half2*)(out + j*4)     = __floats2half2_rn(n0, n1);
        *(__half2*)(out + j*4 + 2) = __floats2half2_rn(n2, n3);
    }
}

// ---------------- init: slots, zero accums, qk0 + lb0 ----------------
__global__ __launch_bounds__(128) void init_q_kernel(
    const float* __restrict__ si,
    const float* __restrict__ Wq, const float* __restrict__ bq,
    const float* __restrict__ gs, const float* __restrict__ bs,
    const float* __restrict__ bk)
{
    __shared__ float sn[128];
    __shared__ float sq[128];
    __shared__ float red[8];
    const int row = blockIdx.x, tid = threadIdx.x;
    const int lane = tid & 31, wrp = tid >> 5;
    float v = si[row*128 + tid];
    g_slots[row*128 + tid] = v;
    g_y[row*128 + tid] = 0.f;
    if (tid == 0) g_rs[row] = 0.f;
    float s = v, ss = v*v;
    #pragma unroll
    for (int o = 16; o; o >>= 1){
        s  += __shfl_xor_sync(0xffffffffu, s, o);
        ss += __shfl_xor_sync(0xffffffffu, ss, o);
    }
    if (lane == 0){ red[wrp] = s; red[4+wrp] = ss; }
    __syncthreads();
    s  = red[0]+red[1]+red[2]+red[3];
    ss = red[4]+red[5]+red[6]+red[7];
    float m = s*(1.f/128.f);
    float rstd = rsqrtf(ss*(1.f/128.f) - m*m + 1e-5f);
    sn[tid] = (v - m)*rstd*gs[tid] + bs[tid];
    __syncthreads();
    float acc = bq[tid];
    {
        const float4* wr  = (const float4*)(Wq + tid*128);
        const float4* sn4 = (const float4*)sn;
        #pragma unroll
        for (int e = 0; e < 32; e++){
            float4 w = wr[e], q = sn4[e];
            acc += w.x*q.x + w.y*q.y + w.z*q.z + w.w*q.w;
        }
    }
    sq[tid] = acc * SCALE;
    __syncthreads();
    float qk = 0.f;
    {
        const float4* wr  = (const float4*)(g_wkT + tid*128);
        const float4* sq4 = (const float4*)sq;
        #pragma unroll
        for (int e = 0; e < 32; e++){
            float4 w = wr[e], q = sq4[e];
            qk += w.x*q.x + w.y*q.y + w.z*q.z + w.w*q.w;
        }
    }
    g_qk[row*128 + tid] = qk;
    float p = sq[tid] * bk[tid];
    #pragma unroll
    for (int o = 16; o; o >>= 1) p += __shfl_xor_sync(0xffffffffu, p, o);
    __syncthreads();
    if (lane == 0) red[wrp] = p;
    __syncthreads();
    if (tid == 0) g_lb[row] = red[0]+red[1]+red[2]+red[3];
}

// ---------------- kernel 3: MMA logits + softmax + MMA y partials ----------------
// 256 threads (8 warps), 256 tokens per block; grid = B * 16
__global__ __launch_bounds__(256) void fused_attn_mma_kernel()
{
    extern __shared__ __align__(16) char smem[];
    const uint32_t sb = smem_u32(smem);
    const int tid = threadIdx.x;
    const int wid = tid >> 5, lane = tid & 31;
    const int bb = blockIdx.x >> 4;
    const int n0 = (blockIdx.x & 15) * 256;

    // ---- stage qk hi/lo + lb ----
    #pragma unroll
    for (int i = 0; i < 4; i++){
        int idx = tid + i*256;                  // 0..1023
        int s = idx >> 7, d = idx & 127;
        float v = g_qk[bb*1024 + idx];
        __half h = __float2half_rn(v);
        __half l = __float2half_rn(v - __half2float(h));
        *(__half*)(smem + SM_QKHI + s*272 + d*2) = h;
        *(__half*)(smem + SM_QKLO + s*272 + d*2) = l;
    }
    if (tid < 8) ((float*)(smem + SM_LB))[tid] = g_lb[bb*8 + tid];

    // ---- stage xn tile (256 x 128 halfs, pitch 272B) ----
    {
        const __half* src = g_xn + (size_t)(bb*4096 + n0)*128;
        #pragma unroll
        for (int i = 0; i < 16; i++){
            int idx = tid + i*256;              // 0..4095
            int r = idx >> 4, c = idx & 15;
            uint4 v = ((const uint4*)(src + (size_t)r*128))[c];
            *(uint4*)(smem + SM_XN + r*272 + c*16) = v;
        }
    }
    __syncthreads();

    // ---- phase 1: logits = xn @ qk^T (hi + lo) ----
    const int aRow  = (lane & 7) + ((lane >> 3) & 1) * 8;
    const int aKoff = (lane >> 4) * 16;
    {
        const int wbase = wid * 32;
        float c[2][4] = {{0.f,0.f,0.f,0.f},{0.f,0.f,0.f,0.f}};
        const uint32_t bAddrH = sb + SM_QKHI + (lane & 7)*272 + ((lane >> 3) & 1)*16;
        const uint32_t bAddrL = bAddrH + (SM_QKLO - SM_QKHI);
        #pragma unroll
        for (int k = 0; k < 8; k++){
            const uint32_t ko = k*32;
            uint32_t bh0,bh1, bl0,bl1;
            LDSM2(bh0,bh1, bAddrH + ko);
            LDSM2(bl0,bl1, bAddrL + ko);
            #pragma unroll
            for (int mt = 0; mt < 2; mt++){
                uint32_t a0,a1,a2,a3;
                LDSM4(a0,a1,a2,a3, sb + SM_XN + (wbase + mt*16 + aRow)*272 + aKoff + ko);
                MMAF16(c[mt], a0,a1,a2,a3, bh0,bh1);
                MMAF16(c[mt], a0,a1,a2,a3, bl0,bl1);
            }
        }
        #pragma unroll
        for (int mt = 0; mt < 2; mt++){
            const int row = wbase + mt*16 + (lane >> 2);
            const int col = (lane & 3) * 2;
            float2 v0; v0.x = c[mt][0]; v0.y = c[mt][1];
            float2 v1; v1.x = c[mt][2]; v1.y = c[mt][3];
            *(float2*)(smem + SM_LG + row*40 + col*4)     = v0;
            *(float2*)(smem + SM_LG + (row+8)*40 + col*4) = v1;
        }
    }
    __syncthreads();

    // ---- softmax (1 token per thread) -> pA hi/lo ----
    {
        const float* lbs = (const float*)(smem + SM_LB);
        const float* lg = (const float*)(smem + SM_LG + tid*40);
        float l[8];
        #pragma unroll
        for (int i = 0; i < 8; i++) l[i] = lg[i] + lbs[i];
        float mx = l[0];
        #pragma unroll
        for (int i = 1; i < 8; i++) mx = fmaxf(mx, l[i]);
        float sum = 0.f;
        #pragma unroll
        for (int i = 0; i < 8; i++){ l[i] = __expf(l[i]-mx); sum += l[i]; }
        float inv = 1.f/sum;
        #pragma unroll
        for (int i = 0; i < 8; i++){
            float p = l[i]*inv + 1e-8f;
            __half h = __float2half_rn(p);
            __half lo = __float2half_rn(p - __half2float(h));
            *(__half*)(smem + SM_PA + i*528 + tid*2)       = h;
            *(__half*)(smem + SM_PA + (i+8)*528 + tid*2)   = lo;
        }
    }
    __syncthreads();

    // ---- rowsum: warp w reduces slot w ----
    {
        const __half2* hi = (const __half2*)(smem + SM_PA + wid*528);
        const __half2* lo = (const __half2*)(smem + SM_PA + (wid+8)*528);
        float r = 0.f;
        #pragma unroll
        for (int i = 0; i < 4; i++){
            float2 a = __half22float2(hi[lane + i*32]);
            float2 b = __half22float2(lo[lane + i*32]);
            r += a.x + a.y + b.x + b.y;
        }
        #pragma unroll
        for (int o = 16; o; o >>= 1) r += __shfl_xor_sync(0xffffffffu, r, o);
        if (lane == 0) atomicAdd(&g_rs[bb*8 + wid], r);
    }

    // ---- phase 2: y = p @ xn  (hi rows 0-7, lo rows 8-15, fold at end) ----
    {
        float c2[2][4] = {{0.f,0.f,0.f,0.f},{0.f,0.f,0.f,0.f}};
        const uint32_t aBase = sb + SM_PA + aRow*528 + aKoff;
        #pragma unroll
        for (int k = 0; k < 16; k++){
            uint32_t a0,a1,a2,a3;
            LDSM4(a0,a1,a2,a3, aBase + k*32);
            #pragma unroll
            for (int nt = 0; nt < 2; nt++){
                const int d_base = (wid*2 + nt)*8;
                uint32_t b0,b1;
                LDSM2T(b0,b1, sb + SM_XN + (k*16 + (lane & 15))*272 + d_base*2);
                MMAF16(c2[nt], a0,a1,a2,a3, b0,b1);
            }
        }
        const int slot = lane >> 2;
        #pragma unroll
        for (int nt = 0; nt < 2; nt++){
            const int col = (wid*2 + nt)*8 + (lane & 3)*2;
            atomicAdd(&g_y[(bb*8+slot)*128 + col],     c2[nt][0] + c2[nt][2]);
            atomicAdd(&g_y[(bb*8+slot)*128 + col + 1], c2[nt][1] + c2[nt][3]);
        }
    }
}

// ---------------- kernel 4: Wv·y + GRU + LN + MLP + next qk/lb; 4 rows/block ----------------
__global__ __launch_bounds__(128) void gru_mlp_q_kernel(
    const float* __restrict__ W_ih, const float* __restrict__ W_hh,
    const float* __restrict__ b_ih, const float* __restrict__ b_hh,
    const float* __restrict__ gm, const float* __restrict__ bm,
    const float* __restrict__ W1, const float* __restrict__ b1,
    const float* __restrict__ W2, const float* __restrict__ b2,
    const float* __restrict__ Wq, const float* __restrict__ bq,
    const float* __restrict__ gs, const float* __restrict__ bs,
    const float* __restrict__ Wv, const float* __restrict__ bv,
    const float* __restrict__ bk)
{
    __shared__ float sa[4][128], sb[4][128], sc[4][128], sy[4][128];
    __shared__ float red_s[4][4], red_ss[4][4];
    const int tid = threadIdx.x;
    const int lane = tid & 31, wrp = tid >> 5;
    const int r0 = blockIdx.x * 4;

    float hv[4], yv[4], rsv[4];
    #pragma unroll
    for (int j = 0; j < 4; j++){
        const int row = r0 + j;
        rsv[j] = g_rs[row];
        yv[j]  = g_y[row*128 + tid];
        hv[j]  = g_slots[row*128 + tid];
    }
    __syncthreads();
    #pragma unroll
    for (int j = 0; j < 4; j++){
        sy[j][tid] = yv[j] / rsv[j];
        g_y[(r0+j)*128 + tid] = 0.f;
    }
    if (tid < 4) g_rs[r0 + tid] = 0.f;
    __syncthreads();

    {
        const float4* wv = (const float4*)(Wv + tid*128);
        const float bvv = bv[tid];
        float uu[4] = {bvv, bvv, bvv, bvv};
        #pragma unroll 4
        for (int e = 0; e < 32; e++){
            float4 w = wv[e];
            #pragma unroll
            for (int j = 0; j < 4; j++){
                float4 x4 = ((const float4*)sy[j])[e];
                uu[j] += w.x*x4.x + w.y*x4.y + w.z*x4.z + w.w*x4.w;
            }
        }
        #pragma unroll
        for (int j = 0; j < 4; j++){ sa[j][tid] = uu[j]; sb[j][tid] = hv[j]; }
    }
    __syncthreads();

    float gi[3][4], gh[3][4];
    #pragma unroll 1
    for (int g = 0; g < 3; g++){
        const float4* wi = (const float4*)(W_ih + (g*128 + tid)*128);
        const float4* wh = (const float4*)(W_hh + (g*128 + tid)*128);
        const float bi = b_ih[g*128 + tid], bh = b_hh[g*128 + tid];
        float ai[4], ah[4];
        #pragma unroll
        for (int j = 0; j < 4; j++){ ai[j] = bi; ah[j] = bh; }
        #pragma unroll 4
        for (int e = 0; e < 32; e++){
            float4 w = wi[e];
            #pragma unroll
            for (int j = 0; j < 4; j++){
                float4 uu = ((const float4*)sa[j])[e];
                ai[j] += w.x*uu.x + w.y*uu.y + w.z*uu.z + w.w*uu.w;
            }
            float4 c = wh[e];
            #pragma unroll
            for (int j = 0; j < 4; j++){
                float4 pp = ((const float4*)sb[j])[e];
                ah[j] += c.x*pp.x + c.y*pp.y + c.z*pp.z + c.w*pp.w;
            }
        }
        #pragma unroll
        for (int j = 0; j < 4; j++){ gi[g][j] = ai[j]; gh[g][j] = ah[j]; }
    }

    float hnv[4];
    #pragma unroll
    for (int j = 0; j < 4; j++){
        float r = 1.f/(1.f + __expf(-(gi[0][j]+gh[0][j])));
        float z = 1.f/(1.f + __expf(-(gi[1][j]+gh[1][j])));
        float n = tanhf(gi[2][j] + r*gh[2][j]);
        hnv[j] = (1.f - z)*n + z*hv[j];
    }

    #pragma unroll
    for (int j = 0; j < 4; j++){
        float s = hnv[j], ss = hnv[j]*hnv[j];
        #pragma unroll
        for (int o = 16; o; o >>= 1){
            s  += __shfl_xor_sync(0xffffffffu, s, o);
            ss += __shfl_xor_sync(0xffffffffu, ss, o);
        }
        if (lane == 0){ red_s[wrp][j] = s; red_ss[wrp][j] = ss; }
    }
    __syncthreads();
    #pragma unroll
    for (int j = 0; j < 4; j++){
        float s  = red_s[0][j]+red_s[1][j]+red_s[2][j]+red_s[3][j];
        float ss = red_ss[0][j]+red_ss[1][j]+red_ss[2][j]+red_ss[3][j];
        float m = s*(1.f/128.f);
        float rstd = rsqrtf(ss*(1.f/128.f) - m*m + 1e-5f);
        sc[j][tid] = (hnv[j] - m)*rstd*gm[tid] + bm[tid];
    }
    __syncthreads();

    {
        const float4* w1 = (const float4*)(W1 + tid*128);
        const float bb1 = b1[tid];
        float hid[4];
        #pragma unroll
        for (int j = 0; j < 4; j++) hid[j] = bb1;
        #pragma unroll 4
        for (int e = 0; e < 32; e++){
            float4 w = w1[e];
            #pragma unroll
            for (int j = 0; j < 4; j++){
                float4 xx = ((const float4*)sc[j])[e];
                hid[j] += w.x*xx.x + w.y*xx.y + w.z*xx.z + w.w*xx.w;
            }
        }
        #pragma unroll
        for (int j = 0; j < 4; j++) sa[j][tid] = fmaxf(hid[j], 0.f);
    }
    __syncthreads();

    float outv[4];
    {
        const float4* w2 = (const float4*)(W2 + tid*128);
        const float bb2 = b2[tid];
        #pragma unroll
        for (int j = 0; j < 4; j++) outv[j] = hnv[j] + bb2;
        #pragma unroll 4
        for (int e = 0; e < 32; e++){
            float4 w = w2[e];
            #pragma unroll
            for (int j = 0; j < 4; j++){
                float4 xx = ((const float4*)sa[j])[e];
                outv[j] += w.x*xx.x + w.y*xx.y + w.z*xx.z + w.w*xx.w;
            }
        }
    }
    #pragma unroll
    for (int j = 0; j < 4; j++)
        g_slots[(r0+j)*128 + tid] = outv[j];
    __syncthreads();

    #pragma unroll
    for (int j = 0; j < 4; j++){
        float s = outv[j], ss = outv[j]*outv[j];
        #pragma unroll
        for (int o = 16; o; o >>= 1){
            s  += __shfl_xor_sync(0xffffffffu, s, o);
            ss += __shfl_xor_sync(0xffffffffu, ss, o);
        }
        if (lane == 0){ red_s[wrp][j] = s; red_ss[wrp][j] = ss; }
    }
    __syncthreads();
    #pragma unroll
    for (int j = 0; j < 4; j++){
        float s  = red_s[0][j]+red_s[1][j]+red_s[2][j]+red_s[3][j];
        float ss = red_ss[0][j]+red_ss[1][j]+red_ss[2][j]+red_ss[3][j];
        float m = s*(1.f/128.f);
        float rstd = rsqrtf(ss*(1.f/128.f) - m*m + 1e-5f);
        sb[j][tid] = (outv[j] - m)*rstd*gs[tid] + bs[tid];
    }
    __syncthreads();
    float qa[4];
    {
        const float4* wq = (const float4*)(Wq + tid*128);
        const float bbq = bq[tid];
        #pragma unroll
        for (int j = 0; j < 4; j++) qa[j] = bbq;
        #pragma unroll 4
        for (int e = 0; e < 32; e++){
            float4 w = wq[e];
            #pragma unroll
            for (int j = 0; j < 4; j++){
                float4 xx = ((const float4*)sb[j])[e];
                qa[j] += w.x*xx.x + w.y*xx.y + w.z*xx.z + w.w*xx.w;
            }
        }
    }
    #pragma unroll
    for (int j = 0; j < 4; j++) sc[j][tid] = qa[j] * SCALE;
    __syncthreads();
    {
        const float4* wkt = (const float4*)(g_wkT + tid*128);
        float qk[4] = {0.f, 0.f, 0.f, 0.f};
        #pragma unroll 4
        for (int e = 0; e < 32; e++){
            float4 w = wkt[e];
            #pragma unroll
            for (int j = 0; j < 4; j++){
                float4 xx = ((const float4*)sc[j])[e];
                qk[j] += w.x*xx.x + w.y*xx.y + w.z*xx.z + w.w*xx.w;
            }
        }
        #pragma unroll
        for (int j = 0; j < 4; j++)
            g_qk[(r0+j)*128 + tid] = qk[j];
    }
    {
        const float bkv = bk[tid];
        #pragma unroll
        for (int j = 0; j < 4; j++){
            float p = sc[j][tid] * bkv;
            #pragma unroll
            for (int o = 16; o; o >>= 1) p += __shfl_xor_sync(0xffffffffu, p, o);
            if (lane == 0) red_s[wrp][j] = p;
        }
    }
    __syncthreads();
    if (tid < 4)
        g_lb[r0 + tid] = red_s[0][tid]+red_s[1][tid]+red_s[2][tid]+red_s[3][tid];
}

// ---------------- launch ----------------
extern "C" void kernel_launch(void* const* d_in, const int* in_sizes, int n_in,
                              void* d_out, int out_size)
{
    const float* x    = (const float*)d_in[0];
    const float* si   = (const float*)d_in[1];
    const float* Wq   = (const float*)d_in[2];
    const float* bq   = (const float*)d_in[3];
    const float* Wk   = (const float*)d_in[4];
    const float* bk   = (const float*)d_in[5];
    const float* Wv   = (const float*)d_in[6];
    const float* bv   = (const float*)d_in[7];
    const float* gin  = (const float*)d_in[8];
    const float* bin  = (const float*)d_in[9];
    const float* gsl  = (const float*)d_in[10];
    const float* bsl  = (const float*)d_in[11];
    const float* gm   = (const float*)d_in[12];
    const float* bm   = (const float*)d_in[13];
    const float* W1   = (const float*)d_in[14];
    const float* b1   = (const float*)d_in[15];
    const float* W2   = (const float*)d_in[16];
    const float* b2   = (const float*)d_in[17];
    const float* W_ih = (const float*)d_in[18];
    const float* W_hh = (const float*)d_in[19];
    const float* b_ih = (const float*)d_in[20];
    const float* b_hh = (const float*)d_in[21];

    static bool attr_set = false;
    if (!attr_set){
        cudaFuncSetAttribute(fused_attn_mma_kernel,
                             cudaFuncAttributeMaxDynamicSharedMemorySize, SM_TOT);
        attr_set = true;
    }

    prep_wkT_kernel<<<64, 256>>>(Wk);
    ln_x_kernel<<<2048, 256>>>(x, gin, bin);
    init_q_kernel<<<512, 128>>>(si, Wq, bq, gsl, bsl, bk);
    for (int it = 0; it < 3; it++){
        fused_attn_mma_kernel<<<1024, 256, SM_TOT>>>();
        gru_mlp_q_kernel<<<128, 128>>>(W_ih, W_hh, b_ih, b_hh, gm, bm,
                                       W1, b1, W2, b2, Wq, bq, gsl, bsl,
                                       Wv, bv, bk);
    }
    export_kernel<<<256, 256>>>((float*)d_out);
}

// round 10
// speedup vs baseline: 2.6729x; 1.4791x over previous
#include <cuda_runtime.h>
#include <cuda_fp16.h>
#include <cstdint>

#define BB 64
#define NN 4096
#define DD 128
#define NS 8
#define SCALE 0.08838834764831845f

// ---------------- device scratch ----------------
__device__ __half g_xn[BB*NN*DD];     // 67 MB fp16 normalized input
__device__ float g_qk[BB*NS*DD];
__device__ float g_lb[BB*NS];
__device__ float g_slots[BB*NS*DD];
__device__ float g_y[BB*NS*DD];
__device__ float g_rs[BB*NS];
__device__ float g_wkT[DD*DD];

__device__ __forceinline__ uint32_t smem_u32(const void* p){
    uint32_t a;
    asm("{ .reg .u64 t; cvta.to.shared.u64 t, %1; cvt.u32.u64 %0, t; }" : "=r"(a) : "l"(p));
    return a;
}
#define LDSM4(r0,r1,r2,r3,addr) \
    asm volatile("ldmatrix.sync.aligned.m8n8.x4.shared.b16 {%0,%1,%2,%3}, [%4];" \
        : "=r"(r0),"=r"(r1),"=r"(r2),"=r"(r3) : "r"(addr))
#define LDSM2(r0,r1,addr) \
    asm volatile("ldmatrix.sync.aligned.m8n8.x2.shared.b16 {%0,%1}, [%2];" \
        : "=r"(r0),"=r"(r1) : "r"(addr))
#define LDSM2T(r0,r1,addr) \
    asm volatile("ldmatrix.sync.aligned.m8n8.x2.trans.shared.b16 {%0,%1}, [%2];" \
        : "=r"(r0),"=r"(r1) : "r"(addr))
#define MMAF16(c,a0,a1,a2,a3,b0,b1) \
    asm volatile("mma.sync.aligned.m16n8k16.row.col.f32.f16.f16.f32 " \
        "{%0,%1,%2,%3}, {%4,%5,%6,%7}, {%8,%9}, {%0,%1,%2,%3};" \
        : "+f"((c)[0]),"+f"((c)[1]),"+f"((c)[2]),"+f"((c)[3]) \
        : "r"(a0),"r"(a1),"r"(a2),"r"(a3),"r"(b0),"r"(b1))

#define SM_QKHI 0
#define SM_QKLO 2176
#define SM_LB   4352
#define SM_LG   4384
#define SM_PA   14624
#define SM_XN   23072
#define SM_TOT  92704

__global__ __launch_bounds__(256) void export_kernel(float* __restrict__ dst){
    int i = blockIdx.x*256 + threadIdx.x;
    dst[i] = g_slots[i];
}
__global__ __launch_bounds__(256) void prep_wkT_kernel(const float* __restrict__ Wk){
    int i = blockIdx.x*256 + threadIdx.x;
    int d = i >> 7, j = i & 127;
    g_wkT[d*128 + j] = Wk[j*128 + d];
}

// ---------------- kernel 1: xn = LN(x) fp16, warp-per-row coalesced ----------------
// grid 32768, 256 threads (8 warps = 8 rows)
__global__ __launch_bounds__(256) void ln_x_kernel(
    const float* __restrict__ x,
    const float* __restrict__ gin, const float* __restrict__ bin)
{
    const int lane = threadIdx.x & 31, wrp = threadIdx.x >> 5;
    const size_t row = (size_t)blockIdx.x*8 + wrp;
    float4 v = ((const float4*)(x + row*128))[lane];
    float s  = v.x + v.y + v.z + v.w;
    float ss = v.x*v.x + v.y*v.y + v.z*v.z + v.w*v.w;
    #pragma unroll
    for (int o = 16; o; o >>= 1){
        s  += __shfl_xor_sync(0xffffffffu, s, o);
        ss += __shfl_xor_sync(0xffffffffu, ss, o);
    }
    const float m = s * (1.f/128.f);
    const float rstd = rsqrtf(ss*(1.f/128.f) - m*m + 1e-5f);
    float4 g4 = ((const float4*)gin)[lane];
    float4 b4 = ((const float4*)bin)[lane];
    float n0 = (v.x - m)*rstd*g4.x + b4.x;
    float n1 = (v.y - m)*rstd*g4.y + b4.y;
    float n2 = (v.z - m)*rstd*g4.z + b4.z;
    float n3 = (v.w - m)*rstd*g4.w + b4.w;
    __half2 h01 = __floats2half2_rn(n0, n1);
    __half2 h23 = __floats2half2_rn(n2, n3);
    uint2 u;
    u.x = *(uint32_t*)&h01;
    u.y = *(uint32_t*)&h23;
    *(uint2*)(g_xn + row*128 + lane*4) = u;
}

// ---------------- init: slots, zero accums, qk0 + lb0 ----------------
__global__ __launch_bounds__(128) void init_q_kernel(
    const float* __restrict__ si,
    const float* __restrict__ Wq, const float* __restrict__ bq,
    const float* __restrict__ gs, const float* __restrict__ bs,
    const float* __restrict__ bk)
{
    __shared__ float sn[128];
    __shared__ float sq[128];
    __shared__ float red[8];
    const int row = blockIdx.x, tid = threadIdx.x;
    const int lane = tid & 31, wrp = tid >> 5;
    float v = si[row*128 + tid];
    g_slots[row*128 + tid] = v;
    g_y[row*128 + tid] = 0.f;
    if (tid == 0) g_rs[row] = 0.f;
    float s = v, ss = v*v;
    #pragma unroll
    for (int o = 16; o; o >>= 1){
        s  += __shfl_xor_sync(0xffffffffu, s, o);
        ss += __shfl_xor_sync(0xffffffffu, ss, o);
    }
    if (lane == 0){ red[wrp] = s; red[4+wrp] = ss; }
    __syncthreads();
    s  = red[0]+red[1]+red[2]+red[3];
    ss = red[4]+red[5]+red[6]+red[7];
    float m = s*(1.f/128.f);
    float rstd = rsqrtf(ss*(1.f/128.f) - m*m + 1e-5f);
    sn[tid] = (v - m)*rstd*gs[tid] + bs[tid];
    __syncthreads();
    float acc = bq[tid];
    {
        const float4* wr  = (const float4*)(Wq + tid*128);
        const float4* sn4 = (const float4*)sn;
        #pragma unroll
        for (int e = 0; e < 32; e++){
            float4 w = wr[e], q = sn4[e];
            acc += w.x*q.x + w.y*q.y + w.z*q.z + w.w*q.w;
        }
    }
    sq[tid] = acc * SCALE;
    __syncthreads();
    float qk = 0.f;
    {
        const float4* wr  = (const float4*)(g_wkT + tid*128);
        const float4* sq4 = (const float4*)sq;
        #pragma unroll
        for (int e = 0; e < 32; e++){
            float4 w = wr[e], q = sq4[e];
            qk += w.x*q.x + w.y*q.y + w.z*q.z + w.w*q.w;
        }
    }
    g_qk[row*128 + tid] = qk;
    float p = sq[tid] * bk[tid];
    #pragma unroll
    for (int o = 16; o; o >>= 1) p += __shfl_xor_sync(0xffffffffu, p, o);
    __syncthreads();
    if (lane == 0) red[wrp] = p;
    __syncthreads();
    if (tid == 0) g_lb[row] = red[0]+red[1]+red[2]+red[3];
}

// ---------------- kernel 3: MMA logits + softmax + MMA y partials (unchanged) ----------------
__global__ __launch_bounds__(256) void fused_attn_mma_kernel()
{
    extern __shared__ __align__(16) char smem[];
    const uint32_t sb = smem_u32(smem);
    const int tid = threadIdx.x;
    const int wid = tid >> 5, lane = tid & 31;
    const int bb = blockIdx.x >> 4;
    const int n0 = (blockIdx.x & 15) * 256;

    #pragma unroll
    for (int i = 0; i < 4; i++){
        int idx = tid + i*256;
        int s = idx >> 7, d = idx & 127;
        float v = g_qk[bb*1024 + idx];
        __half h = __float2half_rn(v);
        __half l = __float2half_rn(v - __half2float(h));
        *(__half*)(smem + SM_QKHI + s*272 + d*2) = h;
        *(__half*)(smem + SM_QKLO + s*272 + d*2) = l;
    }
    if (tid < 8) ((float*)(smem + SM_LB))[tid] = g_lb[bb*8 + tid];

    {
        const __half* src = g_xn + (size_t)(bb*4096 + n0)*128;
        #pragma unroll
        for (int i = 0; i < 16; i++){
            int idx = tid + i*256;
            int r = idx >> 4, c = idx & 15;
            uint4 v = ((const uint4*)(src + (size_t)r*128))[c];
            *(uint4*)(smem + SM_XN + r*272 + c*16) = v;
        }
    }
    __syncthreads();

    const int aRow  = (lane & 7) + ((lane >> 3) & 1) * 8;
    const int aKoff = (lane >> 4) * 16;
    {
        const int wbase = wid * 32;
        float c[2][4] = {{0.f,0.f,0.f,0.f},{0.f,0.f,0.f,0.f}};
        const uint32_t bAddrH = sb + SM_QKHI + (lane & 7)*272 + ((lane >> 3) & 1)*16;
        const uint32_t bAddrL = bAddrH + (SM_QKLO - SM_QKHI);
        #pragma unroll
        for (int k = 0; k < 8; k++){
            const uint32_t ko = k*32;
            uint32_t bh0,bh1, bl0,bl1;
            LDSM2(bh0,bh1, bAddrH + ko);
            LDSM2(bl0,bl1, bAddrL + ko);
            #pragma unroll
            for (int mt = 0; mt < 2; mt++){
                uint32_t a0,a1,a2,a3;
                LDSM4(a0,a1,a2,a3, sb + SM_XN + (wbase + mt*16 + aRow)*272 + aKoff + ko);
                MMAF16(c[mt], a0,a1,a2,a3, bh0,bh1);
                MMAF16(c[mt], a0,a1,a2,a3, bl0,bl1);
            }
        }
        #pragma unroll
        for (int mt = 0; mt < 2; mt++){
            const int row = wbase + mt*16 + (lane >> 2);
            const int col = (lane & 3) * 2;
            float2 v0; v0.x = c[mt][0]; v0.y = c[mt][1];
            float2 v1; v1.x = c[mt][2]; v1.y = c[mt][3];
            *(float2*)(smem + SM_LG + row*40 + col*4)     = v0;
            *(float2*)(smem + SM_LG + (row+8)*40 + col*4) = v1;
        }
    }
    __syncthreads();

    {
        const float* lbs = (const float*)(smem + SM_LB);
        const float* lg = (const float*)(smem + SM_LG + tid*40);
        float l[8];
        #pragma unroll
        for (int i = 0; i < 8; i++) l[i] = lg[i] + lbs[i];
        float mx = l[0];
        #pragma unroll
        for (int i = 1; i < 8; i++) mx = fmaxf(mx, l[i]);
        float sum = 0.f;
        #pragma unroll
        for (int i = 0; i < 8; i++){ l[i] = __expf(l[i]-mx); sum += l[i]; }
        float inv = 1.f/sum;
        #pragma unroll
        for (int i = 0; i < 8; i++){
            float p = l[i]*inv + 1e-8f;
            __half h = __float2half_rn(p);
            __half lo = __float2half_rn(p - __half2float(h));
            *(__half*)(smem + SM_PA + i*528 + tid*2)     = h;
            *(__half*)(smem + SM_PA + (i+8)*528 + tid*2) = lo;
        }
    }
    __syncthreads();

    {
        const __half2* hi = (const __half2*)(smem + SM_PA + wid*528);
        const __half2* lo = (const __half2*)(smem + SM_PA + (wid+8)*528);
        float r = 0.f;
        #pragma unroll
        for (int i = 0; i < 4; i++){
            float2 a = __half22float2(hi[lane + i*32]);
            float2 b = __half22float2(lo[lane + i*32]);
            r += a.x + a.y + b.x + b.y;
        }
        #pragma unroll
        for (int o = 16; o; o >>= 1) r += __shfl_xor_sync(0xffffffffu, r, o);
        if (lane == 0) atomicAdd(&g_rs[bb*8 + wid], r);
    }

    {
        float c2[2][4] = {{0.f,0.f,0.f,0.f},{0.f,0.f,0.f,0.f}};
        const uint32_t aBase = sb + SM_PA + aRow*528 + aKoff;
        #pragma unroll
        for (int k = 0; k < 16; k++){
            uint32_t a0,a1,a2,a3;
            LDSM4(a0,a1,a2,a3, aBase + k*32);
            #pragma unroll
            for (int nt = 0; nt < 2; nt++){
                const int d_base = (wid*2 + nt)*8;
                uint32_t b0,b1;
                LDSM2T(b0,b1, sb + SM_XN + (k*16 + (lane & 15))*272 + d_base*2);
                MMAF16(c2[nt], a0,a1,a2,a3, b0,b1);
            }
        }
        const int slot = lane >> 2;
        #pragma unroll
        for (int nt = 0; nt < 2; nt++){
            const int col = (wid*2 + nt)*8 + (lane & 3)*2;
            atomicAdd(&g_y[(bb*8+slot)*128 + col],     c2[nt][0] + c2[nt][2]);
            atomicAdd(&g_y[(bb*8+slot)*128 + col + 1], c2[nt][1] + c2[nt][3]);
        }
    }
}

// ---------------- kernel 4: GRU+MLP+q, 512 threads, 4-way K-split GEMVs ----------------
__shared__ float s_part[4][4][128];
__global__ __launch_bounds__(512) void gru_mlp_q_kernel(
    const float* __restrict__ W_ih, const float* __restrict__ W_hh,
    const float* __restrict__ b_ih, const float* __restrict__ b_hh,
    const float* __restrict__ gm, const float* __restrict__ bm,
    const float* __restrict__ W1, const float* __restrict__ b1,
    const float* __restrict__ W2, const float* __restrict__ b2,
    const float* __restrict__ Wq, const float* __restrict__ bq,
    const float* __restrict__ gs, const float* __restrict__ bs,
    const float* __restrict__ Wv, const float* __restrict__ bv,
    const float* __restrict__ bk)
{
    __shared__ float spart[4][4][128];    // [kq][row][d]
    __shared__ float sx[4][128];          // GEMV input (stage-dependent)
    __shared__ float sh[4][128];          // prev slots
    __shared__ float su[4][128];          // GRU input u
    __shared__ float red_s[4][4], red_ss[4][4];
    const int tid = threadIdx.x;
    const int d  = tid & 127, kq = tid >> 7;   // kq = 0..3, also row index for loads
    const int lane = tid & 31, wrp = tid >> 5; // wrp 0..3 valid for tid<128
    const int r0 = blockIdx.x * 4;

    // ---- load y/rs/slots (one element per thread), sync, zero ----
    float yv  = g_y[(r0+kq)*128 + d];
    float rsv = g_rs[r0+kq];
    float hvv = g_slots[(r0+kq)*128 + d];
    __syncthreads();
    g_y[(r0+kq)*128 + d] = 0.f;
    if (tid < 4) g_rs[r0+tid] = 0.f;
    sx[kq][d] = yv / rsv;
    sh[kq][d] = hvv;
    __syncthreads();

    // GEMV partial: each thread = one weight-row quarter, all 4 rows
    #define GEMV_PART(WBASE, XIN) do { \
        const float4* w_ = (const float4*)((WBASE) + d*128) + kq*8; \
        float p0=0.f,p1=0.f,p2=0.f,p3=0.f; \
        _Pragma("unroll") \
        for (int e = 0; e < 8; e++){ \
            float4 wv_ = w_[e]; \
            float4 a0 = ((const float4*)(XIN)[0])[kq*8+e]; \
            float4 a1 = ((const float4*)(XIN)[1])[kq*8+e]; \
            float4 a2 = ((const float4*)(XIN)[2])[kq*8+e]; \
            float4 a3 = ((const float4*)(XIN)[3])[kq*8+e]; \
            p0 += wv_.x*a0.x + wv_.y*a0.y + wv_.z*a0.z + wv_.w*a0.w; \
            p1 += wv_.x*a1.x + wv_.y*a1.y + wv_.z*a1.z + wv_.w*a1.w; \
            p2 += wv_.x*a2.x + wv_.y*a2.y + wv_.z*a2.z + wv_.w*a2.w; \
            p3 += wv_.x*a3.x + wv_.y*a3.y + wv_.z*a3.z + wv_.w*a3.w; \
        } \
        spart[kq][0][d]=p0; spart[kq][1][d]=p1; spart[kq][2][d]=p2; spart[kq][3][d]=p3; \
    } while(0)

    #define COMBINE(j) (spart[0][j][tid]+spart[1][j][tid]+spart[2][j][tid]+spart[3][j][tid])

    // ---- u = Wv @ sy + bv -> su ----
    GEMV_PART(Wv, sx);
    __syncthreads();
    if (tid < 128){
        const float bvv = bv[tid];
        #pragma unroll
        for (int j = 0; j < 4; j++) su[j][tid] = bvv + COMBINE(j);
    }
    __syncthreads();

    // ---- GRU gates ----
    float gi[3][4], gh[3][4];
    #pragma unroll 1
    for (int g = 0; g < 3; g++){
        GEMV_PART(W_ih + g*16384, su);
        __syncthreads();
        if (tid < 128){
            const float bi = b_ih[g*128 + tid];
            #pragma unroll
            for (int j = 0; j < 4; j++) gi[g][j] = bi + COMBINE(j);
        }
        __syncthreads();
        GEMV_PART(W_hh + g*16384, sh);
        __syncthreads();
        if (tid < 128){
            const float bh = b_hh[g*128 + tid];
            #pragma unroll
            for (int j = 0; j < 4; j++) gh[g][j] = bh + COMBINE(j);
        }
        __syncthreads();
    }

    // ---- hn + LN(hn) -> sx (MLP input) ----
    float hnv[4];
    if (tid < 128){
        #pragma unroll
        for (int j = 0; j < 4; j++){
            float r = 1.f/(1.f + __expf(-(gi[0][j]+gh[0][j])));
            float z = 1.f/(1.f + __expf(-(gi[1][j]+gh[1][j])));
            float n = tanhf(gi[2][j] + r*gh[2][j]);
            hnv[j] = (1.f - z)*n + z*sh[j][tid];
        }
        #pragma unroll
        for (int j = 0; j < 4; j++){
            float s = hnv[j], ss = hnv[j]*hnv[j];
            #pragma unroll
            for (int o = 16; o; o >>= 1){
                s  += __shfl_xor_sync(0xffffffffu, s, o);
                ss += __shfl_xor_sync(0xffffffffu, ss, o);
            }
            if (lane == 0){ red_s[wrp][j] = s; red_ss[wrp][j] = ss; }
        }
    }
    __syncthreads();
    if (tid < 128){
        #pragma unroll
        for (int j = 0; j < 4; j++){
            float s  = red_s[0][j]+red_s[1][j]+red_s[2][j]+red_s[3][j];
            float ss = red_ss[0][j]+red_ss[1][j]+red_ss[2][j]+red_ss[3][j];
            float m = s*(1.f/128.f);
            float rstd = rsqrtf(ss*(1.f/128.f) - m*m + 1e-5f);
            sx[j][tid] = (hnv[j] - m)*rstd*gm[tid] + bm[tid];
        }
    }
    __syncthreads();

    // ---- MLP layer 1 (relu) -> su (reuse) ----
    GEMV_PART(W1, sx);
    __syncthreads();
    if (tid < 128){
        const float bb1 = b1[tid];
        #pragma unroll
        for (int j = 0; j < 4; j++) su[j][tid] = fmaxf(bb1 + COMBINE(j), 0.f);
    }
    __syncthreads();

    // ---- MLP layer 2 -> out (residual), store slots, LN(out) -> sx ----
    GEMV_PART(W2, su);
    __syncthreads();
    float outv[4];
    if (tid < 128){
        const float bb2 = b2[tid];
        #pragma unroll
        for (int j = 0; j < 4; j++){
            outv[j] = hnv[j] + bb2 + COMBINE(j);
            g_slots[(r0+j)*128 + tid] = outv[j];
        }
        #pragma unroll
        for (int j = 0; j < 4; j++){
            float s = outv[j], ss = outv[j]*outv[j];
            #pragma unroll
            for (int o = 16; o; o >>= 1){
                s  += __shfl_xor_sync(0xffffffffu, s, o);
                ss += __shfl_xor_sync(0xffffffffu, ss, o);
            }
            if (lane == 0){ red_s[wrp][j] = s; red_ss[wrp][j] = ss; }
        }
    }
    __syncthreads();
    if (tid < 128){
        #pragma unroll
        for (int j = 0; j < 4; j++){
            float s  = red_s[0][j]+red_s[1][j]+red_s[2][j]+red_s[3][j];
            float ss = red_ss[0][j]+red_ss[1][j]+red_ss[2][j]+red_ss[3][j];
            float m = s*(1.f/128.f);
            float rstd = rsqrtf(ss*(1.f/128.f) - m*m + 1e-5f);
            sx[j][tid] = (outv[j] - m)*rstd*gs[tid] + bs[tid];
        }
    }
    __syncthreads();

    // ---- q projection -> scaled q in su ----
    GEMV_PART(Wq, sx);
    __syncthreads();
    if (tid < 128){
        const float bbq = bq[tid];
        #pragma unroll
        for (int j = 0; j < 4; j++) su[j][tid] = (bbq + COMBINE(j)) * SCALE;
    }
    __syncthreads();

    // ---- qk = sq @ Wk (via wkT) ----
    GEMV_PART(g_wkT, su);
    __syncthreads();
    if (tid < 128){
        #pragma unroll
        for (int j = 0; j < 4; j++)
            g_qk[(r0+j)*128 + tid] = COMBINE(j);
        // lbias = sq . bk
        const float bkv = bk[tid];
        #pragma unroll
        for (int j = 0; j < 4; j++){
            float p = su[j][tid] * bkv;
            #pragma unroll
            for (int o = 16; o; o >>= 1) p += __shfl_xor_sync(0xffffffffu, p, o);
            if (lane == 0) red_s[wrp][j] = p;
        }
    }
    __syncthreads();
    if (tid < 4)
        g_lb[r0 + tid] = red_s[0][tid]+red_s[1][tid]+red_s[2][tid]+red_s[3][tid];

    #undef GEMV_PART
    #undef COMBINE
}

// ---------------- launch ----------------
extern "C" void kernel_launch(void* const* d_in, const int* in_sizes, int n_in,
                              void* d_out, int out_size)
{
    const float* x    = (const float*)d_in[0];
    const float* si   = (const float*)d_in[1];
    const float* Wq   = (const float*)d_in[2];
    const float* bq   = (const float*)d_in[3];
    const float* Wk   = (const float*)d_in[4];
    const float* bk   = (const float*)d_in[5];
    const float* Wv   = (const float*)d_in[6];
    const float* bv   = (const float*)d_in[7];
    const float* gin  = (const float*)d_in[8];
    const float* bin  = (const float*)d_in[9];
    const float* gsl  = (const float*)d_in[10];
    const float* bsl  = (const float*)d_in[11];
    const float* gm   = (const float*)d_in[12];
    const float* bm   = (const float*)d_in[13];
    const float* W1   = (const float*)d_in[14];
    const float* b1   = (const float*)d_in[15];
    const float* W2   = (const float*)d_in[16];
    const float* b2   = (const float*)d_in[17];
    const float* W_ih = (const float*)d_in[18];
    const float* W_hh = (const float*)d_in[19];
    const float* b_ih = (const float*)d_in[20];
    const float* b_hh = (const float*)d_in[21];

    static bool attr_set = false;
    if (!attr_set){
        cudaFuncSetAttribute(fused_attn_mma_kernel,
                             cudaFuncAttributeMaxDynamicSharedMemorySize, SM_TOT);
        attr_set = true;
    }

    prep_wkT_kernel<<<64, 256>>>(Wk);
    ln_x_kernel<<<32768, 256>>>(x, gin, bin);
    init_q_kernel<<<512, 128>>>(si, Wq, bq, gsl, bsl, bk);
    for (int it = 0; it < 3; it++){
        fused_attn_mma_kernel<<<1024, 256, SM_TOT>>>();
        gru_mlp_q_kernel<<<128, 512>>>(W_ih, W_hh, b_ih, b_hh, gm, bm,
                                       W1, b1, W2, b2, Wq, bq, gsl, bsl,
                                       Wv, bv, bk);
    }
    export_kernel<<<256, 256>>>((float*)d_out);
}